// round 13
// baseline (speedup 1.0000x reference)
#include <cuda_runtime.h>
#include <cuda_fp16.h>
#include <cstdint>

#define T_DIM 2048
#define C_DIM 1024
#define NHEAD 16
#define HSIZE 64
#define KSP   64
#define GQ    16
#define UMAX  128
#define NGRP  ((T_DIM - KSP) / GQ)   // 124

// ---------------- scratch (no allocations allowed) ----------------
__device__ __half   g_qh[T_DIM * C_DIM];   // Q in fp16, pre-scaled by 0.125
__device__ __half   g_kh[T_DIM * C_DIM];
__device__ __half   g_vh[T_DIM * C_DIM];
__device__ float    g_scores[T_DIM];
__device__ int      g_sorted[T_DIM];
__device__ int      g_uidx[NGRP * UMAX];
__device__ int      g_ucnt[NGRP];
__device__ uint32_t g_mask[NGRP * GQ * 4];

__device__ __half g_xq[T_DIM * C_DIM];
__device__ __half g_wq[C_DIM * C_DIM];
__device__ __half g_wk[C_DIM * C_DIM];
__device__ __half g_wv[C_DIM * C_DIM];
__device__ __half g_wo[C_DIM * C_DIM];
__device__ __half g_atq[T_DIM * C_DIM];

// ---------------- helpers ----------------
__device__ __forceinline__ uint32_t smem_to_u32(const void* p) {
    uint32_t a;
    asm("{ .reg .u64 t; cvta.to.shared.u64 t, %1; cvt.u32.u64 %0, t; }" : "=r"(a) : "l"(p));
    return a;
}
#define SW128(off) ((off) ^ (((off) >> 3) & 0x70))
#define SW256(off) ((off) ^ (((off) >> 4) & 0x70))

__device__ __forceinline__ void cp16(uint32_t dst, const void* src) {
    asm volatile("cp.async.cg.shared.global [%0], [%1], 16;" :: "r"(dst), "l"(src));
}
#define CP_COMMIT() asm volatile("cp.async.commit_group;" ::: "memory")
#define CP_WAIT(n)  asm volatile("cp.async.wait_group %0;" :: "n"(n) : "memory")

#define LDSM4(r, addr) \
    asm volatile("ldmatrix.sync.aligned.m8n8.x4.shared.b16 {%0,%1,%2,%3}, [%4];" \
        : "=r"((r)[0]), "=r"((r)[1]), "=r"((r)[2]), "=r"((r)[3]) : "r"(addr))
#define LDSM4_T(r, addr) \
    asm volatile("ldmatrix.sync.aligned.m8n8.x4.trans.shared.b16 {%0,%1,%2,%3}, [%4];" \
        : "=r"((r)[0]), "=r"((r)[1]), "=r"((r)[2]), "=r"((r)[3]) : "r"(addr))

__device__ __forceinline__ void mma16816(float* d, const uint32_t* a, const uint32_t* b) {
    asm volatile("mma.sync.aligned.m16n8k16.row.col.f32.f16.f16.f32 "
        "{%0,%1,%2,%3}, {%4,%5,%6,%7}, {%8,%9}, {%0,%1,%2,%3};"
        : "+f"(d[0]), "+f"(d[1]), "+f"(d[2]), "+f"(d[3])
        : "r"(a[0]), "r"(a[1]), "r"(a[2]), "r"(a[3]), "r"(b[0]), "r"(b[1]));
}

// ---------------------------------------------------------------------------
// Fused input prep: blocks [0, 2048): x->fp16 + key scores; rest: weights.
// ---------------------------------------------------------------------------
#define NW4 (C_DIM * C_DIM / 4)
#define WBLK (NW4 / 256)

__global__ __launch_bounds__(256) void prep_inputs(
    const float4* __restrict__ x4, uint2* __restrict__ xq,
    const float4* __restrict__ wks4, const float* __restrict__ bks,
    const float4* __restrict__ w0, uint2* __restrict__ d0,
    const float4* __restrict__ w1, uint2* __restrict__ d1,
    const float4* __restrict__ w2, uint2* __restrict__ d2,
    const float4* __restrict__ w3, uint2* __restrict__ d3)
{
    const int tid = threadIdx.x;
    const int bx = blockIdx.x;

    if (bx < T_DIM) {
        const int i = bx * 256 + tid;
        float4 v = x4[i];
        __half2 p0 = __floats2half2_rn(v.x, v.y);
        __half2 p1 = __floats2half2_rn(v.z, v.w);
        xq[i] = make_uint2(*reinterpret_cast<uint32_t*>(&p0), *reinterpret_cast<uint32_t*>(&p1));

        float4 wk = wks4[tid];
        float s = v.x * wk.x + v.y * wk.y + v.z * wk.z + v.w * wk.w;
#pragma unroll
        for (int o = 16; o; o >>= 1) s += __shfl_down_sync(0xffffffffu, s, o);
        __shared__ float red[8];
        if ((tid & 31) == 0) red[tid >> 5] = s;
        __syncthreads();
        if (tid == 0) {
            float tot = 0.f;
#pragma unroll
            for (int j = 0; j < 8; j++) tot += red[j];
            g_scores[bx] = tot + bks[0];
        }
    } else {
        const int idx = bx - T_DIM;
        const int which = idx / WBLK;
        const int i = (idx % WBLK) * 256 + tid;
        const float4* src = (which == 0) ? w0 : (which == 1) ? w1 : (which == 2) ? w2 : w3;
        uint2* dst = (which == 0) ? d0 : (which == 1) ? d1 : (which == 2) ? d2 : d3;
        float4 v = src[i];
        __half2 a = __floats2half2_rn(v.x, v.y);
        __half2 b = __floats2half2_rn(v.z, v.w);
        dst[i] = make_uint2(*reinterpret_cast<uint32_t*>(&a), *reinterpret_cast<uint32_t*>(&b));
    }
}

// ---------------------------------------------------------------------------
// Rank-sort body (rides inside gemm_qkv's grid)
// ---------------------------------------------------------------------------
__device__ __forceinline__ void rank_body(char* smem, int rb)
{
    float* ss = reinterpret_cast<float*>(smem);
    const int tid = threadIdx.x;
    for (int i = tid; i < T_DIM; i += 256) ss[i] = g_scores[i];
    __syncthreads();

    const int grpl = tid >> 4;
    const int sub  = tid & 15;
    const int tok = rb * 16 + grpl;
    const float si = ss[tok];

    const float4* s4 = reinterpret_cast<const float4*>(ss);
    int cnt = 0;
    const int j0 = sub * 32;
#pragma unroll 8
    for (int j4 = j0; j4 < j0 + 32; j4++) {
        float4 v = s4[j4];
        int j = j4 << 2;
        cnt += (v.x > si) || (v.x == si && (j + 0) < tok);
        cnt += (v.y > si) || (v.y == si && (j + 1) < tok);
        cnt += (v.z > si) || (v.z == si && (j + 2) < tok);
        cnt += (v.w > si) || (v.w == si && (j + 3) < tok);
    }
#pragma unroll
    for (int o = 8; o; o >>= 1) cnt += __shfl_down_sync(0xffffffffu, cnt, o, 16);
    if (sub == 0) g_sorted[cnt] = tok;
}

// ---------------------------------------------------------------------------
// HMMA GEMM core: D = (Ax*B + bias) * scale. 3-stage, 2 CTAs/SM.
// ---------------------------------------------------------------------------
#define NCHUNK  (C_DIM / 64)
#define TILE_B  16384
#define STAGE_B 32768
#define NSTAGE  3
#define RU      (C_DIM / 8)

template <bool HALF_OUT>
__device__ __forceinline__ void gemm_core(
    const __half* Ax, const __half* B,
    const float* bias, void* outp, int bm, int bn, char* smem, float scale)
{
    const uint32_t sb = smem_to_u32(smem);
    const int tid = threadIdx.x;
    const int wid = tid >> 5;
    const int lane = tid & 31;
    const int warp_m = wid & 3;
    const int warp_n = wid >> 2;

    float acc[2][8][4];
#pragma unroll
    for (int i = 0; i < 2; i++)
#pragma unroll
        for (int j = 0; j < 8; j++)
#pragma unroll
            for (int q = 0; q < 4; q++) acc[i][j][q] = 0.f;

    const uint4* srcs[2] = {
        reinterpret_cast<const uint4*>(Ax) + (size_t)bm * RU,
        reinterpret_cast<const uint4*>(B)  + (size_t)bn * RU };

    const int lrow = tid >> 3;
    const int lch  = tid & 7;

    auto issue = [&](int s, int c) {
        const int kq = c * 8;
        const uint32_t sbase = sb + s * STAGE_B;
#pragma unroll
        for (int t2 = 0; t2 < 2; t2++) {
            const uint4* srow = srcs[t2] + kq;
            const uint32_t dbase = sbase + t2 * TILE_B;
#pragma unroll
            for (int p = 0; p < 4; p++) {
                int row = lrow + p * 32;
                cp16(dbase + SW128(row * 128 + lch * 16),
                     srow + (size_t)row * RU + lch);
            }
        }
        CP_COMMIT();
    };

    issue(0, 0);
    issue(1, 1);
    issue(2, 2);

    const int a_row  = warp_m * 32 + (lane & 15);
    const int a_koff = (lane >> 4) * 16;
    const int b_row  = warp_n * 64 + (lane & 7) + ((lane >> 4) & 1) * 8;
    const int b_koff = ((lane >> 3) & 1) * 16;

    for (int c = 0; c < NCHUNK; c++) {
        const int s = c % NSTAGE;
        if (c < NCHUNK - 2)       { CP_WAIT(2); }
        else if (c == NCHUNK - 2) { CP_WAIT(1); }
        else                      { CP_WAIT(0); }
        __syncthreads();

        const uint32_t aX = sb + s * STAGE_B;
        const uint32_t bB = aX + TILE_B;

#pragma unroll
        for (int ks = 0; ks < 4; ks++) {
            const int akb = ks * 32 + a_koff;
            const int bkb = ks * 32 + b_koff;
            uint32_t ax[2][4], bb[4][4];
#pragma unroll
            for (int mi = 0; mi < 2; mi++) {
                int off = (a_row + mi * 16) * 128 + akb;
                LDSM4(ax[mi], aX + SW128(off));
            }
#pragma unroll
            for (int ni2 = 0; ni2 < 4; ni2++) {
                int off = (b_row + ni2 * 16) * 128 + bkb;
                LDSM4(bb[ni2], bB + SW128(off));
            }
#pragma unroll
            for (int mi = 0; mi < 2; mi++)
#pragma unroll
                for (int ni = 0; ni < 8; ni++)
                    mma16816(acc[mi][ni], ax[mi], &bb[ni >> 1][(ni & 1) * 2]);
        }
        __syncthreads();
        if (c + NSTAGE < NCHUNK) issue(s, c + NSTAGE);
    }

    const int g  = lane >> 2;
    const int tg = lane & 3;
#pragma unroll
    for (int mi = 0; mi < 2; mi++) {
        const int row = bm + warp_m * 32 + mi * 16 + g;
#pragma unroll
        for (int ni = 0; ni < 8; ni++) {
            const int col = bn + warp_n * 64 + ni * 8 + tg * 2;
            float2 bv = *reinterpret_cast<const float2*>(bias + col);
            float o00 = (acc[mi][ni][0] + bv.x) * scale, o01 = (acc[mi][ni][1] + bv.y) * scale;
            float o10 = (acc[mi][ni][2] + bv.x) * scale, o11 = (acc[mi][ni][3] + bv.y) * scale;
            if (HALF_OUT) {
                __half* out = (__half*)outp;
                __half2 h0 = __floats2half2_rn(o00, o01);
                __half2 h1 = __floats2half2_rn(o10, o11);
                *reinterpret_cast<__half2*>(out + (size_t)row * C_DIM + col) = h0;
                *reinterpret_cast<__half2*>(out + (size_t)(row + 8) * C_DIM + col) = h1;
            } else {
                float* out = (float*)outp;
                *reinterpret_cast<float2*>(out + (size_t)row * C_DIM + col) = make_float2(o00, o01);
                *reinterpret_cast<float2*>(out + (size_t)(row + 8) * C_DIM + col) = make_float2(o10, o11);
            }
        }
    }
}

// Fused QKV + rank: grid (32, 16). nb<24: GEMM tiles; nb>=24: rank blocks.
__global__ __launch_bounds__(256, 2) void gemm_qkv(
    const __half* Ax,
    const __half* B0, const float* bias0, __half* out0,
    const __half* B1, const float* bias1, __half* out1,
    const __half* B2, const float* bias2, __half* out2)
{
    extern __shared__ char smem[];
    const int nb = blockIdx.x;
    if (nb >= 24) {
        rank_body(smem, (nb - 24) + blockIdx.y * 8);
        return;
    }
    const int which = nb >> 3;
    const int bn = (nb & 7) << 7;
    const int bm = blockIdx.y << 7;
    if (which == 0) {
        gemm_core<true>(Ax, B0, bias0, out0, bm, bn, smem, 0.125f);  // Q pre-scaled
    } else if (which == 1) {
        gemm_core<true>(Ax, B1, bias1, out1, bm, bn, smem, 1.0f);
    } else {
        gemm_core<true>(Ax, B2, bias2, out2, bm, bn, smem, 1.0f);
    }
}

__global__ __launch_bounds__(256, 2) void gemm_tc(
    const __half* Ax, const __half* B, const float* bias, float* out)
{
    extern __shared__ char smem[];
    gemm_core<false>(Ax, B, bias, out, blockIdx.y << 7, blockIdx.x << 7, smem, 1.0f);
}

// ---------------------------------------------------------------------------
// Per-group union + per-query 128-bit masks (one warp per group)
// ---------------------------------------------------------------------------
__global__ void prep_kernel()
{
    __shared__ int u[UMAX];
    const int g = blockIdx.x;
    const int lane = threadIdx.x;
    const int tmin = KSP + g * GQ;
    const int tmax = tmin + GQ - 1;
    const unsigned lt = (1u << lane) - 1;

    int cmin = 0, kept = 0;
    for (int base = 0; base < T_DIM && cmin < 64; base += 32) {
        int sidx = g_sorted[base + lane];
        bool vmax = (sidx <= tmax);
        unsigned m = __ballot_sync(0xffffffffu, vmax);
        int before = __popc(m & lt);
        if (vmax && kept + before < UMAX) u[kept + before] = sidx;
        kept += __popc(m);
        cmin += __popc(__ballot_sync(0xffffffffu, sidx <= tmin));
    }
    if (kept > UMAX) kept = UMAX;
    if (lane == 0) g_ucnt[g] = kept;
    __syncwarp();

    int uu[4];
#pragma unroll
    for (int c = 0; c < 4; c++) {
        int i = c * 32 + lane;
        uu[c] = (i < kept) ? u[i] : (1 << 30);
        g_uidx[g * UMAX + i] = uu[c];
    }

#pragma unroll 1
    for (int tq = 0; tq < GQ; tq++) {
        int t = tmin + tq;
        int cum = 0;
#pragma unroll
        for (int c = 0; c < 4; c++) {
            bool f = (uu[c] <= t);
            unsigned m = __ballot_sync(0xffffffffu, f);
            int before = __popc(m & lt) + cum;
            unsigned mm = __ballot_sync(0xffffffffu, f && before < 64);
            if (lane == 0) g_mask[(g * GQ + tq) * 4 + c] = mm;
            cum += __popc(m);
        }
    }
}

// ---------------------------------------------------------------------------
// MMA grouped attention, 256 threads (8 warps):
//  - logits: warp w covers 16 key-cols
//  - PV: two warp-quads split the 128 keys; partials combined via SMEM
// ---------------------------------------------------------------------------
struct AttnSmem {
    __half   Kc[128 * 64];   // 16 KB, SW128
    __half   Vc[128 * 64];   // 16 KB, SW128
    __half   Qs[16 * 64];    //  2 KB, SW128
    __half   Ps[16 * 128];   //  4 KB, SW256
    float    Op[2][16][64];  //  8 KB PV partials
    float    pmax[8][16];
    float    psum[8][16];
    int      uidx[UMAX];
    uint32_t mask[GQ][4];
    int      ucnt;
};

__global__ __launch_bounds__(256, 4) void attn_mma_kernel()
{
    extern __shared__ char sm_raw[];
    AttnSmem& S = *reinterpret_cast<AttnSmem*>(sm_raw);

    const int grp = blockIdx.x;
    const int h   = blockIdx.y;
    const bool small = (grp >= NGRP);
    const int t0  = small ? (grp - NGRP) * GQ : KSP + grp * GQ;
    const int base = h * HSIZE;
    const int tid = threadIdx.x;
    const int w = tid >> 5;
    const int lane = tid & 31;

    if (small) {
        if (tid == 0) S.ucnt = 64;
        if (tid < 64) S.uidx[tid] = tid;
    } else {
        if (tid == 0) S.ucnt = g_ucnt[grp];
        if (tid < UMAX) S.uidx[tid] = g_uidx[grp * UMAX + tid];
        if (tid < 64)
            S.mask[tid >> 2][tid & 3] = g_mask[(grp * GQ + (tid >> 2)) * 4 + (tid & 3)];
    }
    __syncthreads();
    const int ucnt = S.ucnt;

    const uint32_t kbase = smem_to_u32(S.Kc);
    const uint32_t vbase = smem_to_u32(S.Vc);
    const uint32_t qbase = smem_to_u32(S.Qs);
    const uint32_t pbase = smem_to_u32(S.Ps);
    char* kc = reinterpret_cast<char*>(S.Kc);
    char* vc = reinterpret_cast<char*>(S.Vc);
    char* qc = reinterpret_cast<char*>(S.Qs);
    char* pc = reinterpret_cast<char*>(S.Ps);

    // stage K/V (zero-pad to 128 rows), 8 threads/row, 32 rows/pass
    const int c8 = tid & 7;
    for (int r = tid >> 3; r < 128; r += 32) {
        uint4 kk = make_uint4(0, 0, 0, 0), vv = kk;
        if (r < ucnt) {
            int tok = S.uidx[r];
            kk = *((const uint4*)(g_kh + (size_t)tok * C_DIM + base) + c8);
            vv = *((const uint4*)(g_vh + (size_t)tok * C_DIM + base) + c8);
        }
        *reinterpret_cast<uint4*>(kc + SW128(r * 128 + c8 * 16)) = kk;
        *reinterpret_cast<uint4*>(vc + SW128(r * 128 + c8 * 16)) = vv;
    }
    if (tid < 128) {   // Q: 16 rows x 8 chunks
        int r = tid >> 3;
        uint4 qq = *((const uint4*)(g_qh + (size_t)(t0 + r) * C_DIM + base) + c8);
        *reinterpret_cast<uint4*>(qc + SW128(r * 128 + c8 * 16)) = qq;
    }
    __syncthreads();

    const int a_row = lane & 15;
    const int a_k16 = (lane >> 4) * 16;
    const int b_row = (lane & 7) + ((lane >> 4) & 1) * 8;
    const int b_k16 = ((lane >> 3) & 1) * 16;
    const int g  = lane >> 2;
    const int tg = lane & 3;

    // ---- logits: warp w covers keys [w*16, w*16+16) ----
    float d[2][4];
#pragma unroll
    for (int i = 0; i < 2; i++)
#pragma unroll
        for (int j = 0; j < 4; j++) d[i][j] = 0.f;

#pragma unroll
    for (int ks = 0; ks < 4; ks++) {
        uint32_t aq[4];
        LDSM4(aq, qbase + SW128(a_row * 128 + ks * 32 + a_k16));
        uint32_t bk[4];
        LDSM4(bk, kbase + SW128((w * 16 + b_row) * 128 + ks * 32 + b_k16));
        mma16816(d[0], aq, &bk[0]);
        mma16816(d[1], aq, &bk[2]);
    }

    // row max over this warp's 16 keys
    float m0 = fmaxf(fmaxf(d[0][0], d[0][1]), fmaxf(d[1][0], d[1][1]));
    float m1 = fmaxf(fmaxf(d[0][2], d[0][3]), fmaxf(d[1][2], d[1][3]));
    m0 = fmaxf(m0, __shfl_xor_sync(0xffffffffu, m0, 1));
    m0 = fmaxf(m0, __shfl_xor_sync(0xffffffffu, m0, 2));
    m1 = fmaxf(m1, __shfl_xor_sync(0xffffffffu, m1, 1));
    m1 = fmaxf(m1, __shfl_xor_sync(0xffffffffu, m1, 2));
    if (tg == 0) { S.pmax[w][g] = m0; S.pmax[w][8 + g] = m1; }
    __syncthreads();
    float gm0 = S.pmax[0][g], gm1 = S.pmax[0][8 + g];
#pragma unroll
    for (int i = 1; i < 8; i++) {
        gm0 = fmaxf(gm0, S.pmax[i][g]);
        gm1 = fmaxf(gm1, S.pmax[i][8 + g]);
    }

    // weighted exp (mask = top-64 selection; small groups use min(j,t) weights)
    const int tA = t0 + g, tB = t0 + 8 + g;
    float ws0 = 0.f, ws1 = 0.f;
#pragma unroll
    for (int ni = 0; ni < 2; ni++) {
        int col = w * 16 + ni * 8 + tg * 2;
        float wA0, wA1, wB0, wB1;
        if (small) {
            wA0 = (col < tA) ? 1.f : ((col == tA) ? (float)(64 - tA) : 0.f);
            wA1 = (col + 1 < tA) ? 1.f : ((col + 1 == tA) ? (float)(64 - tA) : 0.f);
            wB0 = (col < tB) ? 1.f : ((col == tB) ? (float)(64 - tB) : 0.f);
            wB1 = (col + 1 < tB) ? 1.f : ((col + 1 == tB) ? (float)(64 - tB) : 0.f);
        } else {
            uint32_t mwA = S.mask[g][col >> 5];
            uint32_t mwB = S.mask[8 + g][col >> 5];
            int bit = col & 31;
            wA0 = (float)((mwA >> bit) & 1u);
            wA1 = (float)((mwA >> (bit + 1)) & 1u);
            wB0 = (float)((mwB >> bit) & 1u);
            wB1 = (float)((mwB >> (bit + 1)) & 1u);
        }
        d[ni][0] = expf(d[ni][0] - gm0) * wA0;  ws0 += d[ni][0];
        d[ni][1] = expf(d[ni][1] - gm0) * wA1;  ws0 += d[ni][1];
        d[ni][2] = expf(d[ni][2] - gm1) * wB0;  ws1 += d[ni][2];
        d[ni][3] = expf(d[ni][3] - gm1) * wB1;  ws1 += d[ni][3];
    }
    ws0 += __shfl_xor_sync(0xffffffffu, ws0, 1);
    ws0 += __shfl_xor_sync(0xffffffffu, ws0, 2);
    ws1 += __shfl_xor_sync(0xffffffffu, ws1, 1);
    ws1 += __shfl_xor_sync(0xffffffffu, ws1, 2);
    if (tg == 0) { S.psum[w][g] = ws0; S.psum[w][8 + g] = ws1; }
    __syncthreads();
    float sm0 = 0.f, sm1 = 0.f;
#pragma unroll
    for (int i = 0; i < 8; i++) { sm0 += S.psum[i][g]; sm1 += S.psum[i][8 + g]; }
    float inv0 = 1.f / sm0, inv1 = 1.f / sm1;

    // store P (fp16, SW256 rows of 256B)
#pragma unroll
    for (int ni = 0; ni < 2; ni++) {
        int col = w * 16 + ni * 8 + tg * 2;
        *reinterpret_cast<__half2*>(pc + SW256(g * 256 + col * 2)) =
            __floats2half2_rn(d[ni][0] * inv0, d[ni][1] * inv0);
        *reinterpret_cast<__half2*>(pc + SW256((8 + g) * 256 + col * 2)) =
            __floats2half2_rn(d[ni][2] * inv1, d[ni][3] * inv1);
    }
    __syncthreads();

    // ---- PV: warp-quad kslot covers keys [kslot*64, +64); dims dw*16..+16 ----
    const int kslot = w >> 2;
    const int dw = w & 3;
    float o[2][4];
#pragma unroll
    for (int i = 0; i < 2; i++)
#pragma unroll
        for (int j = 0; j < 4; j++) o[i][j] = 0.f;

    const int v_row = (lane & 7) + ((lane >> 3) & 1) * 8;
    const int v_d16 = ((lane >> 4) & 1) * 16;

#pragma unroll
    for (int k4 = 0; k4 < 4; k4++) {
        const int ks = kslot * 4 + k4;
        uint32_t ap[4];
        LDSM4(ap, pbase + SW256(a_row * 256 + ks * 32 + a_k16));
        uint32_t bv[4];
        LDSM4_T(bv, vbase + SW128((ks * 16 + v_row) * 128 + dw * 32 + v_d16));
        mma16816(o[0], ap, &bv[0]);
        mma16816(o[1], ap, &bv[2]);
    }

#pragma unroll
    for (int ni = 0; ni < 2; ni++) {
        int col = dw * 16 + ni * 8 + tg * 2;
        S.Op[kslot][g][col]     = o[ni][0];
        S.Op[kslot][g][col + 1] = o[ni][1];
        S.Op[kslot][8 + g][col]     = o[ni][2];
        S.Op[kslot][8 + g][col + 1] = o[ni][3];
    }
    __syncthreads();

    // combine halves + store: 256 threads x 4 outputs
    {
        const int idx = tid << 2;
        const int row = idx >> 6;
        const int col = idx & 63;
        float4 aL = *reinterpret_cast<float4*>(&S.Op[0][row][col]);
        float4 aH = *reinterpret_cast<float4*>(&S.Op[1][row][col]);
        __half2 h0 = __floats2half2_rn(aL.x + aH.x, aL.y + aH.y);
        __half2 h1 = __floats2half2_rn(aL.z + aH.z, aL.w + aH.w);
        uint2 st = make_uint2(*reinterpret_cast<uint32_t*>(&h0),
                              *reinterpret_cast<uint32_t*>(&h1));
        *reinterpret_cast<uint2*>(g_atq + (size_t)(t0 + row) * C_DIM + base + col) = st;
    }
}

// ---------------------------------------------------------------------------
extern "C" void kernel_launch(void* const* d_in, const int* in_sizes, int n_in,
                              void* d_out, int out_size)
{
    const float* x   = (const float*)d_in[0];
    const float* Wq  = (const float*)d_in[1];
    const float* bq  = (const float*)d_in[2];
    const float* Wk  = (const float*)d_in[3];
    const float* bk  = (const float*)d_in[4];
    const float* Wv  = (const float*)d_in[5];
    const float* bv  = (const float*)d_in[6];
    const float* Wo  = (const float*)d_in[7];
    const float* bo  = (const float*)d_in[8];
    const float* Wks = (const float*)d_in[9];
    const float* bks = (const float*)d_in[10];
    float* out = (float*)d_out;

    __half *qh, *kh, *vh;
    cudaGetSymbolAddress((void**)&qh, g_qh);
    cudaGetSymbolAddress((void**)&kh, g_kh);
    cudaGetSymbolAddress((void**)&vh, g_vh);

    __half *xq, *wq, *wk, *wv, *wo, *atq;
    cudaGetSymbolAddress((void**)&xq,  g_xq);
    cudaGetSymbolAddress((void**)&wq,  g_wq);
    cudaGetSymbolAddress((void**)&wk,  g_wk);
    cudaGetSymbolAddress((void**)&wv,  g_wv);
    cudaGetSymbolAddress((void**)&wo,  g_wo);
    cudaGetSymbolAddress((void**)&atq, g_atq);

    const int gemm_smem = NSTAGE * STAGE_B;       // 98304
    const int attn_smem = (int)sizeof(AttnSmem);  // ~49KB
    static bool attr_done = false;
    if (!attr_done) {
        cudaFuncSetAttribute(gemm_qkv, cudaFuncAttributeMaxDynamicSharedMemorySize, gemm_smem);
        cudaFuncSetAttribute(gemm_tc,  cudaFuncAttributeMaxDynamicSharedMemorySize, gemm_smem);
        cudaFuncSetAttribute(attn_mma_kernel, cudaFuncAttributeMaxDynamicSharedMemorySize, attn_smem);
        attr_done = true;
    }

    prep_inputs<<<T_DIM + 4 * WBLK, 256>>>(
        (const float4*)x, (uint2*)xq, (const float4*)Wks, bks,
        (const float4*)Wq, (uint2*)wq,
        (const float4*)Wk, (uint2*)wk,
        (const float4*)Wv, (uint2*)wv,
        (const float4*)Wo, (uint2*)wo);

    gemm_qkv<<<dim3(32, 16), 256, gemm_smem>>>(
        xq,
        wq, bq, qh,
        wk, bk, kh,
        wv, bv, vh);

    prep_kernel<<<NGRP, 32>>>();

    attn_mma_kernel<<<dim3(NGRP + KSP / GQ, NHEAD), 256, attn_smem>>>();

    gemm_tc<<<dim3(8, 16), 256, gemm_smem>>>(atq, wo, bo, out);
}

// round 14
// speedup vs baseline: 1.0947x; 1.0947x over previous
#include <cuda_runtime.h>
#include <cuda_fp16.h>
#include <cstdint>

#define T_DIM 2048
#define C_DIM 1024
#define NHEAD 16
#define HSIZE 64
#define KSP   64
#define GQ    16
#define UMAX  128
#define NGRP  ((T_DIM - KSP) / GQ)   // 124

// ---------------- scratch (no allocations allowed) ----------------
__device__ __half   g_qh[T_DIM * C_DIM];   // Q in fp16, pre-scaled by 0.125
__device__ __half   g_kh[T_DIM * C_DIM];
__device__ __half   g_vh[T_DIM * C_DIM];
__device__ float    g_scores[T_DIM];
__device__ int      g_sorted[T_DIM];

__device__ __half g_xq[T_DIM * C_DIM];
__device__ __half g_wq[C_DIM * C_DIM];
__device__ __half g_wk[C_DIM * C_DIM];
__device__ __half g_wv[C_DIM * C_DIM];
__device__ __half g_wo[C_DIM * C_DIM];
__device__ __half g_atq[T_DIM * C_DIM];

// ---------------- helpers ----------------
__device__ __forceinline__ uint32_t smem_to_u32(const void* p) {
    uint32_t a;
    asm("{ .reg .u64 t; cvta.to.shared.u64 t, %1; cvt.u32.u64 %0, t; }" : "=r"(a) : "l"(p));
    return a;
}
#define SW128(off) ((off) ^ (((off) >> 3) & 0x70))
#define SW256(off) ((off) ^ (((off) >> 4) & 0x70))

__device__ __forceinline__ void cp16(uint32_t dst, const void* src) {
    asm volatile("cp.async.cg.shared.global [%0], [%1], 16;" :: "r"(dst), "l"(src));
}
#define CP_COMMIT() asm volatile("cp.async.commit_group;" ::: "memory")
#define CP_WAIT(n)  asm volatile("cp.async.wait_group %0;" :: "n"(n) : "memory")

#define LDSM4(r, addr) \
    asm volatile("ldmatrix.sync.aligned.m8n8.x4.shared.b16 {%0,%1,%2,%3}, [%4];" \
        : "=r"((r)[0]), "=r"((r)[1]), "=r"((r)[2]), "=r"((r)[3]) : "r"(addr))
#define LDSM4_T(r, addr) \
    asm volatile("ldmatrix.sync.aligned.m8n8.x4.trans.shared.b16 {%0,%1,%2,%3}, [%4];" \
        : "=r"((r)[0]), "=r"((r)[1]), "=r"((r)[2]), "=r"((r)[3]) : "r"(addr))

__device__ __forceinline__ void mma16816(float* d, const uint32_t* a, const uint32_t* b) {
    asm volatile("mma.sync.aligned.m16n8k16.row.col.f32.f16.f16.f32 "
        "{%0,%1,%2,%3}, {%4,%5,%6,%7}, {%8,%9}, {%0,%1,%2,%3};"
        : "+f"(d[0]), "+f"(d[1]), "+f"(d[2]), "+f"(d[3])
        : "r"(a[0]), "r"(a[1]), "r"(a[2]), "r"(a[3]), "r"(b[0]), "r"(b[1]));
}

// ---------------------------------------------------------------------------
// Fused input prep: blocks [0, 2048): x->fp16 + key scores; rest: weights.
// ---------------------------------------------------------------------------
#define NW4 (C_DIM * C_DIM / 4)
#define WBLK (NW4 / 256)

__global__ __launch_bounds__(256) void prep_inputs(
    const float4* __restrict__ x4, uint2* __restrict__ xq,
    const float4* __restrict__ wks4, const float* __restrict__ bks,
    const float4* __restrict__ w0, uint2* __restrict__ d0,
    const float4* __restrict__ w1, uint2* __restrict__ d1,
    const float4* __restrict__ w2, uint2* __restrict__ d2,
    const float4* __restrict__ w3, uint2* __restrict__ d3)
{
    const int tid = threadIdx.x;
    const int bx = blockIdx.x;

    if (bx < T_DIM) {
        const int i = bx * 256 + tid;
        float4 v = x4[i];
        __half2 p0 = __floats2half2_rn(v.x, v.y);
        __half2 p1 = __floats2half2_rn(v.z, v.w);
        xq[i] = make_uint2(*reinterpret_cast<uint32_t*>(&p0), *reinterpret_cast<uint32_t*>(&p1));

        float4 wk = wks4[tid];
        float s = v.x * wk.x + v.y * wk.y + v.z * wk.z + v.w * wk.w;
#pragma unroll
        for (int o = 16; o; o >>= 1) s += __shfl_down_sync(0xffffffffu, s, o);
        __shared__ float red[8];
        if ((tid & 31) == 0) red[tid >> 5] = s;
        __syncthreads();
        if (tid == 0) {
            float tot = 0.f;
#pragma unroll
            for (int j = 0; j < 8; j++) tot += red[j];
            g_scores[bx] = tot + bks[0];
        }
    } else {
        const int idx = bx - T_DIM;
        const int which = idx / WBLK;
        const int i = (idx % WBLK) * 256 + tid;
        const float4* src = (which == 0) ? w0 : (which == 1) ? w1 : (which == 2) ? w2 : w3;
        uint2* dst = (which == 0) ? d0 : (which == 1) ? d1 : (which == 2) ? d2 : d3;
        float4 v = src[i];
        __half2 a = __floats2half2_rn(v.x, v.y);
        __half2 b = __floats2half2_rn(v.z, v.w);
        dst[i] = make_uint2(*reinterpret_cast<uint32_t*>(&a), *reinterpret_cast<uint32_t*>(&b));
    }
}

// ---------------------------------------------------------------------------
// Rank-sort body (rides inside gemm_qkv's grid)
// ---------------------------------------------------------------------------
__device__ __forceinline__ void rank_body(char* smem, int rb)
{
    float* ss = reinterpret_cast<float*>(smem);
    const int tid = threadIdx.x;
    for (int i = tid; i < T_DIM; i += 256) ss[i] = g_scores[i];
    __syncthreads();

    const int grpl = tid >> 4;
    const int sub  = tid & 15;
    const int tok = rb * 16 + grpl;
    const float si = ss[tok];

    const float4* s4 = reinterpret_cast<const float4*>(ss);
    int cnt = 0;
    const int j0 = sub * 32;
#pragma unroll 8
    for (int j4 = j0; j4 < j0 + 32; j4++) {
        float4 v = s4[j4];
        int j = j4 << 2;
        cnt += (v.x > si) || (v.x == si && (j + 0) < tok);
        cnt += (v.y > si) || (v.y == si && (j + 1) < tok);
        cnt += (v.z > si) || (v.z == si && (j + 2) < tok);
        cnt += (v.w > si) || (v.w == si && (j + 3) < tok);
    }
#pragma unroll
    for (int o = 8; o; o >>= 1) cnt += __shfl_down_sync(0xffffffffu, cnt, o, 16);
    if (sub == 0) g_sorted[cnt] = tok;
}

// ---------------------------------------------------------------------------
// HMMA GEMM core: D = (Ax*B + bias) * scale. 3-stage, 2 CTAs/SM.
// ---------------------------------------------------------------------------
#define NCHUNK  (C_DIM / 64)
#define TILE_B  16384
#define STAGE_B 32768
#define NSTAGE  3
#define RU      (C_DIM / 8)

template <bool HALF_OUT>
__device__ __forceinline__ void gemm_core(
    const __half* Ax, const __half* B,
    const float* bias, void* outp, int bm, int bn, char* smem, float scale)
{
    const uint32_t sb = smem_to_u32(smem);
    const int tid = threadIdx.x;
    const int wid = tid >> 5;
    const int lane = tid & 31;
    const int warp_m = wid & 3;
    const int warp_n = wid >> 2;

    float acc[2][8][4];
#pragma unroll
    for (int i = 0; i < 2; i++)
#pragma unroll
        for (int j = 0; j < 8; j++)
#pragma unroll
            for (int q = 0; q < 4; q++) acc[i][j][q] = 0.f;

    const uint4* srcs[2] = {
        reinterpret_cast<const uint4*>(Ax) + (size_t)bm * RU,
        reinterpret_cast<const uint4*>(B)  + (size_t)bn * RU };

    const int lrow = tid >> 3;
    const int lch  = tid & 7;

    auto issue = [&](int s, int c) {
        const int kq = c * 8;
        const uint32_t sbase = sb + s * STAGE_B;
#pragma unroll
        for (int t2 = 0; t2 < 2; t2++) {
            const uint4* srow = srcs[t2] + kq;
            const uint32_t dbase = sbase + t2 * TILE_B;
#pragma unroll
            for (int p = 0; p < 4; p++) {
                int row = lrow + p * 32;
                cp16(dbase + SW128(row * 128 + lch * 16),
                     srow + (size_t)row * RU + lch);
            }
        }
        CP_COMMIT();
    };

    issue(0, 0);
    issue(1, 1);
    issue(2, 2);

    const int a_row  = warp_m * 32 + (lane & 15);
    const int a_koff = (lane >> 4) * 16;
    const int b_row  = warp_n * 64 + (lane & 7) + ((lane >> 4) & 1) * 8;
    const int b_koff = ((lane >> 3) & 1) * 16;

    for (int c = 0; c < NCHUNK; c++) {
        const int s = c % NSTAGE;
        if (c < NCHUNK - 2)       { CP_WAIT(2); }
        else if (c == NCHUNK - 2) { CP_WAIT(1); }
        else                      { CP_WAIT(0); }
        __syncthreads();

        const uint32_t aX = sb + s * STAGE_B;
        const uint32_t bB = aX + TILE_B;

#pragma unroll
        for (int ks = 0; ks < 4; ks++) {
            const int akb = ks * 32 + a_koff;
            const int bkb = ks * 32 + b_koff;
            uint32_t ax[2][4], bb[4][4];
#pragma unroll
            for (int mi = 0; mi < 2; mi++) {
                int off = (a_row + mi * 16) * 128 + akb;
                LDSM4(ax[mi], aX + SW128(off));
            }
#pragma unroll
            for (int ni2 = 0; ni2 < 4; ni2++) {
                int off = (b_row + ni2 * 16) * 128 + bkb;
                LDSM4(bb[ni2], bB + SW128(off));
            }
#pragma unroll
            for (int mi = 0; mi < 2; mi++)
#pragma unroll
                for (int ni = 0; ni < 8; ni++)
                    mma16816(acc[mi][ni], ax[mi], &bb[ni >> 1][(ni & 1) * 2]);
        }
        __syncthreads();
        if (c + NSTAGE < NCHUNK) issue(s, c + NSTAGE);
    }

    const int g  = lane >> 2;
    const int tg = lane & 3;
#pragma unroll
    for (int mi = 0; mi < 2; mi++) {
        const int row = bm + warp_m * 32 + mi * 16 + g;
#pragma unroll
        for (int ni = 0; ni < 8; ni++) {
            const int col = bn + warp_n * 64 + ni * 8 + tg * 2;
            float2 bv = *reinterpret_cast<const float2*>(bias + col);
            float o00 = (acc[mi][ni][0] + bv.x) * scale, o01 = (acc[mi][ni][1] + bv.y) * scale;
            float o10 = (acc[mi][ni][2] + bv.x) * scale, o11 = (acc[mi][ni][3] + bv.y) * scale;
            if (HALF_OUT) {
                __half* out = (__half*)outp;
                __half2 h0 = __floats2half2_rn(o00, o01);
                __half2 h1 = __floats2half2_rn(o10, o11);
                *reinterpret_cast<__half2*>(out + (size_t)row * C_DIM + col) = h0;
                *reinterpret_cast<__half2*>(out + (size_t)(row + 8) * C_DIM + col) = h1;
            } else {
                float* out = (float*)outp;
                *reinterpret_cast<float2*>(out + (size_t)row * C_DIM + col) = make_float2(o00, o01);
                *reinterpret_cast<float2*>(out + (size_t)(row + 8) * C_DIM + col) = make_float2(o10, o11);
            }
        }
    }
}

// Fused QKV + rank: grid (32, 16). nb<24: GEMM tiles; nb>=24: rank blocks.
__global__ __launch_bounds__(256, 2) void gemm_qkv(
    const __half* Ax,
    const __half* B0, const float* bias0, __half* out0,
    const __half* B1, const float* bias1, __half* out1,
    const __half* B2, const float* bias2, __half* out2)
{
    extern __shared__ char smem[];
    const int nb = blockIdx.x;
    if (nb >= 24) {
        rank_body(smem, (nb - 24) + blockIdx.y * 8);
        return;
    }
    const int which = nb >> 3;
    const int bn = (nb & 7) << 7;
    const int bm = blockIdx.y << 7;
    if (which == 0) {
        gemm_core<true>(Ax, B0, bias0, out0, bm, bn, smem, 0.125f);  // Q pre-scaled
    } else if (which == 1) {
        gemm_core<true>(Ax, B1, bias1, out1, bm, bn, smem, 1.0f);
    } else {
        gemm_core<true>(Ax, B2, bias2, out2, bm, bn, smem, 1.0f);
    }
}

__global__ __launch_bounds__(256, 2) void gemm_tc(
    const __half* Ax, const __half* B, const float* bias, float* out)
{
    extern __shared__ char smem[];
    gemm_core<false>(Ax, B, bias, out, blockIdx.y << 7, blockIdx.x << 7, smem, 1.0f);
}

// ---------------------------------------------------------------------------
// MMA grouped attention (R12 structure, 128 thr / 4 warps) with in-block
// union + mask computation (prep_kernel folded in) and Ps overlaid on Qs.
// ---------------------------------------------------------------------------
struct AttnSmem {
    __half   Kc[128 * 64];   // 16 KB, SW128
    __half   Vc[128 * 64];   // 16 KB, SW128
    union {
        __half Qs[16 * 64];  //  2 KB, SW128 (dead after logits)
        __half Ps[16 * 128]; //  4 KB, SW256
    };
    float    pmax[4][16];
    float    psum[4][16];
    int      uidx[UMAX];
    uint32_t mask[GQ][4];
    int      ucnt;
};

__global__ __launch_bounds__(128, 6) void attn_mma_kernel()
{
    extern __shared__ char sm_raw[];
    AttnSmem& S = *reinterpret_cast<AttnSmem*>(sm_raw);

    const int grp = blockIdx.x;
    const int h   = blockIdx.y;
    const bool small = (grp >= NGRP);
    const int t0  = small ? (grp - NGRP) * GQ : KSP + grp * GQ;
    const int base = h * HSIZE;
    const int tid = threadIdx.x;
    const int w = tid >> 5;
    const int lane = tid & 31;
    const unsigned ltm = (1u << lane) - 1;

    // ---- union (warp 0) ----
    if (small) {
        if (tid == 0) S.ucnt = 64;
        if (tid < 64) S.uidx[tid] = tid;
    } else if (w == 0) {
        const int tmin = t0;
        const int tmax = t0 + GQ - 1;
        int cmin = 0, kept = 0;
        for (int b = 0; b < T_DIM && cmin < 64; b += 32) {
            int sidx = g_sorted[b + lane];
            bool vmax = (sidx <= tmax);
            unsigned m = __ballot_sync(0xffffffffu, vmax);
            int before = __popc(m & ltm);
            if (vmax && kept + before < UMAX) S.uidx[kept + before] = sidx;
            kept += __popc(m);
            cmin += __popc(__ballot_sync(0xffffffffu, sidx <= tmin));
        }
        if (kept > UMAX) kept = UMAX;
        if (lane == 0) S.ucnt = kept;
        for (int i = kept + lane; i < UMAX; i += 32) S.uidx[i] = 1 << 30;
    }
    __syncthreads();
    const int ucnt = S.ucnt;

    const uint32_t kbase = smem_to_u32(S.Kc);
    const uint32_t vbase = smem_to_u32(S.Vc);
    const uint32_t qbase = smem_to_u32(S.Qs);
    const uint32_t pbase = smem_to_u32(S.Ps);
    char* kc = reinterpret_cast<char*>(S.Kc);
    char* vc = reinterpret_cast<char*>(S.Vc);
    char* qc = reinterpret_cast<char*>(S.Qs);
    char* pc = reinterpret_cast<char*>(S.Ps);

    // stage K/V (zero-pad to 128 rows), 8 threads/row
    const int c8 = tid & 7;
    for (int r = tid >> 3; r < 128; r += 16) {
        uint4 kk = make_uint4(0, 0, 0, 0), vv = kk;
        if (r < ucnt) {
            int tok = S.uidx[r];
            kk = *((const uint4*)(g_kh + (size_t)tok * C_DIM + base) + c8);
            vv = *((const uint4*)(g_vh + (size_t)tok * C_DIM + base) + c8);
        }
        *reinterpret_cast<uint4*>(kc + SW128(r * 128 + c8 * 16)) = kk;
        *reinterpret_cast<uint4*>(vc + SW128(r * 128 + c8 * 16)) = vv;
    }
    {   // Q: 16 rows x 8 chunks
        int r = tid >> 3;
        uint4 qq = *((const uint4*)(g_qh + (size_t)(t0 + r) * C_DIM + base) + c8);
        *reinterpret_cast<uint4*>(qc + SW128(r * 128 + c8 * 16)) = qq;
    }

    // ---- masks: warp w computes queries w*4 .. w*4+3 ----
    if (!small) {
#pragma unroll
        for (int j = 0; j < 4; j++) {
            const int q = w * 4 + j;
            const int t = t0 + q;
            int cum = 0;
#pragma unroll
            for (int c = 0; c < 4; c++) {
                int val = S.uidx[c * 32 + lane];
                bool f = (val <= t);
                unsigned m = __ballot_sync(0xffffffffu, f);
                int before = __popc(m & ltm) + cum;
                unsigned mm = __ballot_sync(0xffffffffu, f && before < 64);
                if (lane == 0) S.mask[q][c] = mm;
                cum += __popc(m);
            }
        }
    }
    __syncthreads();

    // ---- logits: warp w covers keys [w*32, w*32+32) ----
    float d[4][4];
#pragma unroll
    for (int i = 0; i < 4; i++)
#pragma unroll
        for (int j = 0; j < 4; j++) d[i][j] = 0.f;

    const int a_row = lane & 15;
    const int a_k16 = (lane >> 4) * 16;
    const int b_row = (lane & 7) + ((lane >> 4) & 1) * 8;
    const int b_k16 = ((lane >> 3) & 1) * 16;

#pragma unroll
    for (int ks = 0; ks < 4; ks++) {
        uint32_t aq[4];
        LDSM4(aq, qbase + SW128(a_row * 128 + ks * 32 + a_k16));
        uint32_t bk[2][4];
#pragma unroll
        for (int ni2 = 0; ni2 < 2; ni2++)
            LDSM4(bk[ni2], kbase + SW128((w * 32 + ni2 * 16 + b_row) * 128 + ks * 32 + b_k16));
#pragma unroll
        for (int ni = 0; ni < 4; ni++)
            mma16816(d[ni], aq, &bk[ni >> 1][(ni & 1) * 2]);
    }

    const int g  = lane >> 2;
    const int tg = lane & 3;

    // row max over this warp's 32 keys
    float m0 = -1e30f, m1 = -1e30f;
#pragma unroll
    for (int ni = 0; ni < 4; ni++) {
        m0 = fmaxf(m0, fmaxf(d[ni][0], d[ni][1]));
        m1 = fmaxf(m1, fmaxf(d[ni][2], d[ni][3]));
    }
    m0 = fmaxf(m0, __shfl_xor_sync(0xffffffffu, m0, 1));
    m0 = fmaxf(m0, __shfl_xor_sync(0xffffffffu, m0, 2));
    m1 = fmaxf(m1, __shfl_xor_sync(0xffffffffu, m1, 1));
    m1 = fmaxf(m1, __shfl_xor_sync(0xffffffffu, m1, 2));
    if (tg == 0) { S.pmax[w][g] = m0; S.pmax[w][8 + g] = m1; }
    __syncthreads();
    float gm0 = fmaxf(fmaxf(S.pmax[0][g], S.pmax[1][g]), fmaxf(S.pmax[2][g], S.pmax[3][g]));
    float gm1 = fmaxf(fmaxf(S.pmax[0][8 + g], S.pmax[1][8 + g]), fmaxf(S.pmax[2][8 + g], S.pmax[3][8 + g]));

    // weighted exp
    uint32_t mw0 = 0, mw1 = 0;
    if (!small) { mw0 = S.mask[g][w]; mw1 = S.mask[8 + g][w]; }
    const int tA = t0 + g, tB = t0 + 8 + g;
    float ws0 = 0.f, ws1 = 0.f;
#pragma unroll
    for (int ni = 0; ni < 4; ni++) {
        int colL = ni * 8 + tg * 2;
        int col  = w * 32 + colL;
        float wA0, wA1, wB0, wB1;
        if (small) {
            wA0 = (col < tA) ? 1.f : ((col == tA) ? (float)(64 - tA) : 0.f);
            wA1 = (col + 1 < tA) ? 1.f : ((col + 1 == tA) ? (float)(64 - tA) : 0.f);
            wB0 = (col < tB) ? 1.f : ((col == tB) ? (float)(64 - tB) : 0.f);
            wB1 = (col + 1 < tB) ? 1.f : ((col + 1 == tB) ? (float)(64 - tB) : 0.f);
        } else {
            wA0 = (float)((mw0 >> colL) & 1u);
            wA1 = (float)((mw0 >> (colL + 1)) & 1u);
            wB0 = (float)((mw1 >> colL) & 1u);
            wB1 = (float)((mw1 >> (colL + 1)) & 1u);
        }
        d[ni][0] = expf(d[ni][0] - gm0) * wA0;  ws0 += d[ni][0];
        d[ni][1] = expf(d[ni][1] - gm0) * wA1;  ws0 += d[ni][1];
        d[ni][2] = expf(d[ni][2] - gm1) * wB0;  ws1 += d[ni][2];
        d[ni][3] = expf(d[ni][3] - gm1) * wB1;  ws1 += d[ni][3];
    }
    ws0 += __shfl_xor_sync(0xffffffffu, ws0, 1);
    ws0 += __shfl_xor_sync(0xffffffffu, ws0, 2);
    ws1 += __shfl_xor_sync(0xffffffffu, ws1, 1);
    ws1 += __shfl_xor_sync(0xffffffffu, ws1, 2);
    if (tg == 0) { S.psum[w][g] = ws0; S.psum[w][8 + g] = ws1; }
    __syncthreads();
    float inv0 = 1.f / (S.psum[0][g] + S.psum[1][g] + S.psum[2][g] + S.psum[3][g]);
    float inv1 = 1.f / (S.psum[0][8 + g] + S.psum[1][8 + g] + S.psum[2][8 + g] + S.psum[3][8 + g]);

    // store P (fp16, SW256 rows of 256B) — overlays dead Qs
#pragma unroll
    for (int ni = 0; ni < 4; ni++) {
        int col = w * 32 + ni * 8 + tg * 2;
        *reinterpret_cast<__half2*>(pc + SW256(g * 256 + col * 2)) =
            __floats2half2_rn(d[ni][0] * inv0, d[ni][1] * inv0);
        *reinterpret_cast<__half2*>(pc + SW256((8 + g) * 256 + col * 2)) =
            __floats2half2_rn(d[ni][2] * inv1, d[ni][3] * inv1);
    }
    __syncthreads();

    // ---- PV: warp w covers dims [w*16, w*16+16) ----
    float o[2][4];
#pragma unroll
    for (int i = 0; i < 2; i++)
#pragma unroll
        for (int j = 0; j < 4; j++) o[i][j] = 0.f;

    const int v_row = (lane & 7) + ((lane >> 3) & 1) * 8;
    const int v_d16 = ((lane >> 4) & 1) * 16;

#pragma unroll
    for (int ks = 0; ks < 8; ks++) {
        uint32_t ap[4];
        LDSM4(ap, pbase + SW256(a_row * 256 + ks * 32 + a_k16));
        uint32_t bv[4];
        LDSM4_T(bv, vbase + SW128((ks * 16 + v_row) * 128 + w * 32 + v_d16));
        mma16816(o[0], ap, &bv[0]);
        mma16816(o[1], ap, &bv[2]);
    }

#pragma unroll
    for (int ni = 0; ni < 2; ni++) {
        int col = w * 16 + ni * 8 + tg * 2;
        *reinterpret_cast<__half2*>(g_atq + (size_t)(t0 + g) * C_DIM + base + col) =
            __floats2half2_rn(o[ni][0], o[ni][1]);
        *reinterpret_cast<__half2*>(g_atq + (size_t)(t0 + 8 + g) * C_DIM + base + col) =
            __floats2half2_rn(o[ni][2], o[ni][3]);
    }
}

// ---------------------------------------------------------------------------
extern "C" void kernel_launch(void* const* d_in, const int* in_sizes, int n_in,
                              void* d_out, int out_size)
{
    const float* x   = (const float*)d_in[0];
    const float* Wq  = (const float*)d_in[1];
    const float* bq  = (const float*)d_in[2];
    const float* Wk  = (const float*)d_in[3];
    const float* bk  = (const float*)d_in[4];
    const float* Wv  = (const float*)d_in[5];
    const float* bv  = (const float*)d_in[6];
    const float* Wo  = (const float*)d_in[7];
    const float* bo  = (const float*)d_in[8];
    const float* Wks = (const float*)d_in[9];
    const float* bks = (const float*)d_in[10];
    float* out = (float*)d_out;

    __half *qh, *kh, *vh;
    cudaGetSymbolAddress((void**)&qh, g_qh);
    cudaGetSymbolAddress((void**)&kh, g_kh);
    cudaGetSymbolAddress((void**)&vh, g_vh);

    __half *xq, *wq, *wk, *wv, *wo, *atq;
    cudaGetSymbolAddress((void**)&xq,  g_xq);
    cudaGetSymbolAddress((void**)&wq,  g_wq);
    cudaGetSymbolAddress((void**)&wk,  g_wk);
    cudaGetSymbolAddress((void**)&wv,  g_wv);
    cudaGetSymbolAddress((void**)&wo,  g_wo);
    cudaGetSymbolAddress((void**)&atq, g_atq);

    const int gemm_smem = NSTAGE * STAGE_B;       // 98304
    const int attn_smem = (int)sizeof(AttnSmem);  // ~37.3KB
    static bool attr_done = false;
    if (!attr_done) {
        cudaFuncSetAttribute(gemm_qkv, cudaFuncAttributeMaxDynamicSharedMemorySize, gemm_smem);
        cudaFuncSetAttribute(gemm_tc,  cudaFuncAttributeMaxDynamicSharedMemorySize, gemm_smem);
        cudaFuncSetAttribute(attn_mma_kernel, cudaFuncAttributeMaxDynamicSharedMemorySize, attn_smem);
        attr_done = true;
    }

    prep_inputs<<<T_DIM + 4 * WBLK, 256>>>(
        (const float4*)x, (uint2*)xq, (const float4*)Wks, bks,
        (const float4*)Wq, (uint2*)wq,
        (const float4*)Wk, (uint2*)wk,
        (const float4*)Wv, (uint2*)wv,
        (const float4*)Wo, (uint2*)wo);

    gemm_qkv<<<dim3(32, 16), 256, gemm_smem>>>(
        xq,
        wq, bq, qh,
        wk, bk, kh,
        wv, bv, vh);

    attn_mma_kernel<<<dim3(NGRP + KSP / GQ, NHEAD), 128, attn_smem>>>();

    gemm_tc<<<dim3(8, 16), 256, gemm_smem>>>(atq, wo, bo, out);
}

// round 15
// speedup vs baseline: 1.0967x; 1.0019x over previous
#include <cuda_runtime.h>
#include <cuda_fp16.h>
#include <cstdint>

#define T_DIM 2048
#define C_DIM 1024
#define NHEAD 16
#define HSIZE 64
#define KSP   64
#define GQ    16
#define UMAX  128
#define NGRP  ((T_DIM - KSP) / GQ)   // 124

// ---------------- scratch (no allocations allowed) ----------------
__device__ __half   g_qh[T_DIM * C_DIM];   // Q in fp16, pre-scaled by 0.125
__device__ __half   g_kh[T_DIM * C_DIM];
__device__ __half   g_vh[T_DIM * C_DIM];
__device__ float    g_scores[T_DIM];
__device__ int      g_sorted[T_DIM];

__device__ __half g_xq[T_DIM * C_DIM];
__device__ __half g_wq[C_DIM * C_DIM];
__device__ __half g_wk[C_DIM * C_DIM];
__device__ __half g_wv[C_DIM * C_DIM];
__device__ __half g_wo[C_DIM * C_DIM];
__device__ __half g_atq[T_DIM * C_DIM];

// ---------------- helpers ----------------
__device__ __forceinline__ uint32_t smem_to_u32(const void* p) {
    uint32_t a;
    asm("{ .reg .u64 t; cvta.to.shared.u64 t, %1; cvt.u32.u64 %0, t; }" : "=r"(a) : "l"(p));
    return a;
}
#define SW128(off) ((off) ^ (((off) >> 3) & 0x70))
#define SW256(off) ((off) ^ (((off) >> 4) & 0x70))

__device__ __forceinline__ void cp16(uint32_t dst, const void* src) {
    asm volatile("cp.async.cg.shared.global [%0], [%1], 16;" :: "r"(dst), "l"(src));
}
#define CP_COMMIT() asm volatile("cp.async.commit_group;" ::: "memory")
#define CP_WAIT(n)  asm volatile("cp.async.wait_group %0;" :: "n"(n) : "memory")

#define LDSM4(r, addr) \
    asm volatile("ldmatrix.sync.aligned.m8n8.x4.shared.b16 {%0,%1,%2,%3}, [%4];" \
        : "=r"((r)[0]), "=r"((r)[1]), "=r"((r)[2]), "=r"((r)[3]) : "r"(addr))
#define LDSM4_T(r, addr) \
    asm volatile("ldmatrix.sync.aligned.m8n8.x4.trans.shared.b16 {%0,%1,%2,%3}, [%4];" \
        : "=r"((r)[0]), "=r"((r)[1]), "=r"((r)[2]), "=r"((r)[3]) : "r"(addr))

__device__ __forceinline__ void mma16816(float* d, const uint32_t* a, const uint32_t* b) {
    asm volatile("mma.sync.aligned.m16n8k16.row.col.f32.f16.f16.f32 "
        "{%0,%1,%2,%3}, {%4,%5,%6,%7}, {%8,%9}, {%0,%1,%2,%3};"
        : "+f"(d[0]), "+f"(d[1]), "+f"(d[2]), "+f"(d[3])
        : "r"(a[0]), "r"(a[1]), "r"(a[2]), "r"(a[3]), "r"(b[0]), "r"(b[1]));
}

// ---------------------------------------------------------------------------
// Fused input prep: blocks [0, 2048): x->fp16 + key scores; rest: weights.
// ---------------------------------------------------------------------------
#define NW4 (C_DIM * C_DIM / 4)
#define WBLK (NW4 / 256)

__global__ __launch_bounds__(256) void prep_inputs(
    const float4* __restrict__ x4, uint2* __restrict__ xq,
    const float4* __restrict__ wks4, const float* __restrict__ bks,
    const float4* __restrict__ w0, uint2* __restrict__ d0,
    const float4* __restrict__ w1, uint2* __restrict__ d1,
    const float4* __restrict__ w2, uint2* __restrict__ d2,
    const float4* __restrict__ w3, uint2* __restrict__ d3)
{
    const int tid = threadIdx.x;
    const int bx = blockIdx.x;

    if (bx < T_DIM) {
        const int i = bx * 256 + tid;
        float4 v = x4[i];
        __half2 p0 = __floats2half2_rn(v.x, v.y);
        __half2 p1 = __floats2half2_rn(v.z, v.w);
        xq[i] = make_uint2(*reinterpret_cast<uint32_t*>(&p0), *reinterpret_cast<uint32_t*>(&p1));

        float4 wk = wks4[tid];
        float s = v.x * wk.x + v.y * wk.y + v.z * wk.z + v.w * wk.w;
#pragma unroll
        for (int o = 16; o; o >>= 1) s += __shfl_down_sync(0xffffffffu, s, o);
        __shared__ float red[8];
        if ((tid & 31) == 0) red[tid >> 5] = s;
        __syncthreads();
        if (tid == 0) {
            float tot = 0.f;
#pragma unroll
            for (int j = 0; j < 8; j++) tot += red[j];
            g_scores[bx] = tot + bks[0];
        }
    } else {
        const int idx = bx - T_DIM;
        const int which = idx / WBLK;
        const int i = (idx % WBLK) * 256 + tid;
        const float4* src = (which == 0) ? w0 : (which == 1) ? w1 : (which == 2) ? w2 : w3;
        uint2* dst = (which == 0) ? d0 : (which == 1) ? d1 : (which == 2) ? d2 : d3;
        float4 v = src[i];
        __half2 a = __floats2half2_rn(v.x, v.y);
        __half2 b = __floats2half2_rn(v.z, v.w);
        dst[i] = make_uint2(*reinterpret_cast<uint32_t*>(&a), *reinterpret_cast<uint32_t*>(&b));
    }
}

// ---------------------------------------------------------------------------
// Rank-sort body (rides inside gemm_qkv's grid)
// ---------------------------------------------------------------------------
__device__ __forceinline__ void rank_body(char* smem, int rb)
{
    float* ss = reinterpret_cast<float*>(smem);
    const int tid = threadIdx.x;
    for (int i = tid; i < T_DIM; i += 256) ss[i] = g_scores[i];
    __syncthreads();

    const int grpl = tid >> 4;
    const int sub  = tid & 15;
    const int tok = rb * 16 + grpl;
    const float si = ss[tok];

    const float4* s4 = reinterpret_cast<const float4*>(ss);
    int cnt = 0;
    const int j0 = sub * 32;
#pragma unroll 8
    for (int j4 = j0; j4 < j0 + 32; j4++) {
        float4 v = s4[j4];
        int j = j4 << 2;
        cnt += (v.x > si) || (v.x == si && (j + 0) < tok);
        cnt += (v.y > si) || (v.y == si && (j + 1) < tok);
        cnt += (v.z > si) || (v.z == si && (j + 2) < tok);
        cnt += (v.w > si) || (v.w == si && (j + 3) < tok);
    }
#pragma unroll
    for (int o = 8; o; o >>= 1) cnt += __shfl_down_sync(0xffffffffu, cnt, o, 16);
    if (sub == 0) g_sorted[cnt] = tok;
}

// ---------------------------------------------------------------------------
// HMMA GEMM core (128x128): D = (Ax*B + bias) * scale. 3-stage, 2 CTAs/SM.
// ---------------------------------------------------------------------------
#define NCHUNK  (C_DIM / 64)
#define TILE_B  16384
#define STAGE_B 32768
#define NSTAGE  3
#define RU      (C_DIM / 8)

template <bool HALF_OUT>
__device__ __forceinline__ void gemm_core(
    const __half* Ax, const __half* B,
    const float* bias, void* outp, int bm, int bn, char* smem, float scale)
{
    const uint32_t sb = smem_to_u32(smem);
    const int tid = threadIdx.x;
    const int wid = tid >> 5;
    const int lane = tid & 31;
    const int warp_m = wid & 3;
    const int warp_n = wid >> 2;

    float acc[2][8][4];
#pragma unroll
    for (int i = 0; i < 2; i++)
#pragma unroll
        for (int j = 0; j < 8; j++)
#pragma unroll
            for (int q = 0; q < 4; q++) acc[i][j][q] = 0.f;

    const uint4* srcs[2] = {
        reinterpret_cast<const uint4*>(Ax) + (size_t)bm * RU,
        reinterpret_cast<const uint4*>(B)  + (size_t)bn * RU };

    const int lrow = tid >> 3;
    const int lch  = tid & 7;

    auto issue = [&](int s, int c) {
        const int kq = c * 8;
        const uint32_t sbase = sb + s * STAGE_B;
#pragma unroll
        for (int t2 = 0; t2 < 2; t2++) {
            const uint4* srow = srcs[t2] + kq;
            const uint32_t dbase = sbase + t2 * TILE_B;
#pragma unroll
            for (int p = 0; p < 4; p++) {
                int row = lrow + p * 32;
                cp16(dbase + SW128(row * 128 + lch * 16),
                     srow + (size_t)row * RU + lch);
            }
        }
        CP_COMMIT();
    };

    issue(0, 0);
    issue(1, 1);
    issue(2, 2);

    const int a_row  = warp_m * 32 + (lane & 15);
    const int a_koff = (lane >> 4) * 16;
    const int b_row  = warp_n * 64 + (lane & 7) + ((lane >> 4) & 1) * 8;
    const int b_koff = ((lane >> 3) & 1) * 16;

    for (int c = 0; c < NCHUNK; c++) {
        const int s = c % NSTAGE;
        if (c < NCHUNK - 2)       { CP_WAIT(2); }
        else if (c == NCHUNK - 2) { CP_WAIT(1); }
        else                      { CP_WAIT(0); }
        __syncthreads();

        const uint32_t aX = sb + s * STAGE_B;
        const uint32_t bB = aX + TILE_B;

#pragma unroll
        for (int ks = 0; ks < 4; ks++) {
            const int akb = ks * 32 + a_koff;
            const int bkb = ks * 32 + b_koff;
            uint32_t ax[2][4], bb[4][4];
#pragma unroll
            for (int mi = 0; mi < 2; mi++) {
                int off = (a_row + mi * 16) * 128 + akb;
                LDSM4(ax[mi], aX + SW128(off));
            }
#pragma unroll
            for (int ni2 = 0; ni2 < 4; ni2++) {
                int off = (b_row + ni2 * 16) * 128 + bkb;
                LDSM4(bb[ni2], bB + SW128(off));
            }
#pragma unroll
            for (int mi = 0; mi < 2; mi++)
#pragma unroll
                for (int ni = 0; ni < 8; ni++)
                    mma16816(acc[mi][ni], ax[mi], &bb[ni >> 1][(ni & 1) * 2]);
        }
        __syncthreads();
        if (c + NSTAGE < NCHUNK) issue(s, c + NSTAGE);
    }

    const int g  = lane >> 2;
    const int tg = lane & 3;
#pragma unroll
    for (int mi = 0; mi < 2; mi++) {
        const int row = bm + warp_m * 32 + mi * 16 + g;
#pragma unroll
        for (int ni = 0; ni < 8; ni++) {
            const int col = bn + warp_n * 64 + ni * 8 + tg * 2;
            float2 bv = *reinterpret_cast<const float2*>(bias + col);
            float o00 = (acc[mi][ni][0] + bv.x) * scale, o01 = (acc[mi][ni][1] + bv.y) * scale;
            float o10 = (acc[mi][ni][2] + bv.x) * scale, o11 = (acc[mi][ni][3] + bv.y) * scale;
            if (HALF_OUT) {
                __half* out = (__half*)outp;
                __half2 h0 = __floats2half2_rn(o00, o01);
                __half2 h1 = __floats2half2_rn(o10, o11);
                *reinterpret_cast<__half2*>(out + (size_t)row * C_DIM + col) = h0;
                *reinterpret_cast<__half2*>(out + (size_t)(row + 8) * C_DIM + col) = h1;
            } else {
                float* out = (float*)outp;
                *reinterpret_cast<float2*>(out + (size_t)row * C_DIM + col) = make_float2(o00, o01);
                *reinterpret_cast<float2*>(out + (size_t)(row + 8) * C_DIM + col) = make_float2(o10, o11);
            }
        }
    }
}

// Fused QKV + rank: grid (32, 16). nb<24: GEMM tiles; nb>=24: rank blocks.
__global__ __launch_bounds__(256, 2) void gemm_qkv(
    const __half* Ax,
    const __half* B0, const float* bias0, __half* out0,
    const __half* B1, const float* bias1, __half* out1,
    const __half* B2, const float* bias2, __half* out2)
{
    extern __shared__ char smem[];
    const int nb = blockIdx.x;
    if (nb >= 24) {
        rank_body(smem, (nb - 24) + blockIdx.y * 8);
        return;
    }
    const int which = nb >> 3;
    const int bn = (nb & 7) << 7;
    const int bm = blockIdx.y << 7;
    if (which == 0) {
        gemm_core<true>(Ax, B0, bias0, out0, bm, bn, smem, 0.125f);  // Q pre-scaled
    } else if (which == 1) {
        gemm_core<true>(Ax, B1, bias1, out1, bm, bn, smem, 1.0f);
    } else {
        gemm_core<true>(Ax, B2, bias2, out2, bm, bn, smem, 1.0f);
    }
}

// ---------------------------------------------------------------------------
// Output GEMM: BM=64, BN=128 tiles, grid (8, 32) = 256 CTAs, 2 CTAs/SM.
// 8 warps as 2m x 4n, warp tile 32x32. Stage = 24KB (A 8KB + B 16KB).
// ---------------------------------------------------------------------------
#define ATILE_O 8192
#define STAGE_O 24576

__global__ __launch_bounds__(256, 2) void gemm_out(
    const __half* __restrict__ Ax, const __half* __restrict__ B,
    const float* __restrict__ bias, float* __restrict__ out)
{
    extern __shared__ char smem[];
    const uint32_t sb = smem_to_u32(smem);
    const int tid = threadIdx.x;
    const int wid = tid >> 5;
    const int lane = tid & 31;
    const int warp_m = wid & 1;
    const int warp_n = wid >> 1;
    const int bm = blockIdx.y << 6;
    const int bn = blockIdx.x << 7;

    float acc[2][4][4];
#pragma unroll
    for (int i = 0; i < 2; i++)
#pragma unroll
        for (int j = 0; j < 4; j++)
#pragma unroll
            for (int q = 0; q < 4; q++) acc[i][j][q] = 0.f;

    const uint4* srcA = reinterpret_cast<const uint4*>(Ax) + (size_t)bm * RU;
    const uint4* srcB = reinterpret_cast<const uint4*>(B)  + (size_t)bn * RU;

    const int lrow = tid >> 3;   // 0..31
    const int lch  = tid & 7;

    auto issue = [&](int s, int c) {
        const int kq = c * 8;
        const uint32_t sbase = sb + s * STAGE_O;
#pragma unroll
        for (int p = 0; p < 2; p++) {       // A: 64 rows
            int row = lrow + p * 32;
            cp16(sbase + SW128(row * 128 + lch * 16),
                 srcA + (size_t)row * RU + kq + lch);
        }
#pragma unroll
        for (int p = 0; p < 4; p++) {       // B: 128 rows
            int row = lrow + p * 32;
            cp16(sbase + ATILE_O + SW128(row * 128 + lch * 16),
                 srcB + (size_t)row * RU + kq + lch);
        }
        CP_COMMIT();
    };

    issue(0, 0);
    issue(1, 1);
    issue(2, 2);

    const int a_row  = warp_m * 32 + (lane & 15);
    const int a_koff = (lane >> 4) * 16;
    const int b_row  = warp_n * 32 + (lane & 7) + ((lane >> 4) & 1) * 8;
    const int b_koff = ((lane >> 3) & 1) * 16;

    for (int c = 0; c < NCHUNK; c++) {
        const int s = c % NSTAGE;
        if (c < NCHUNK - 2)       { CP_WAIT(2); }
        else if (c == NCHUNK - 2) { CP_WAIT(1); }
        else                      { CP_WAIT(0); }
        __syncthreads();

        const uint32_t aX = sb + s * STAGE_O;
        const uint32_t bB = aX + ATILE_O;

#pragma unroll
        for (int ks = 0; ks < 4; ks++) {
            const int akb = ks * 32 + a_koff;
            const int bkb = ks * 32 + b_koff;
            uint32_t ax[2][4], bb[2][4];
#pragma unroll
            for (int mi = 0; mi < 2; mi++) {
                int off = (a_row + mi * 16) * 128 + akb;
                LDSM4(ax[mi], aX + SW128(off));
            }
#pragma unroll
            for (int ni2 = 0; ni2 < 2; ni2++) {
                int off = (b_row + ni2 * 16) * 128 + bkb;
                LDSM4(bb[ni2], bB + SW128(off));
            }
#pragma unroll
            for (int mi = 0; mi < 2; mi++)
#pragma unroll
                for (int ni = 0; ni < 4; ni++)
                    mma16816(acc[mi][ni], ax[mi], &bb[ni >> 1][(ni & 1) * 2]);
        }
        __syncthreads();
        if (c + NSTAGE < NCHUNK) issue(s, c + NSTAGE);
    }

    const int g  = lane >> 2;
    const int tg = lane & 3;
#pragma unroll
    for (int mi = 0; mi < 2; mi++) {
        const int row = bm + warp_m * 32 + mi * 16 + g;
#pragma unroll
        for (int ni = 0; ni < 4; ni++) {
            const int col = bn + warp_n * 32 + ni * 8 + tg * 2;
            float2 bv = *reinterpret_cast<const float2*>(bias + col);
            *reinterpret_cast<float2*>(out + (size_t)row * C_DIM + col) =
                make_float2(acc[mi][ni][0] + bv.x, acc[mi][ni][1] + bv.y);
            *reinterpret_cast<float2*>(out + (size_t)(row + 8) * C_DIM + col) =
                make_float2(acc[mi][ni][2] + bv.x, acc[mi][ni][3] + bv.y);
        }
    }
}

// ---------------------------------------------------------------------------
// MMA grouped attention (128 thr / 4 warps), union+masks in-block, Ps on Qs.
// ---------------------------------------------------------------------------
struct AttnSmem {
    __half   Kc[128 * 64];   // 16 KB, SW128
    __half   Vc[128 * 64];   // 16 KB, SW128
    union {
        __half Qs[16 * 64];  //  2 KB, SW128 (dead after logits)
        __half Ps[16 * 128]; //  4 KB, SW256
    };
    float    pmax[4][16];
    float    psum[4][16];
    int      uidx[UMAX];
    uint32_t mask[GQ][4];
    int      ucnt;
};

__global__ __launch_bounds__(128, 6) void attn_mma_kernel()
{
    extern __shared__ char sm_raw[];
    AttnSmem& S = *reinterpret_cast<AttnSmem*>(sm_raw);

    const int grp = blockIdx.x;
    const int h   = blockIdx.y;
    const bool small = (grp >= NGRP);
    const int t0  = small ? (grp - NGRP) * GQ : KSP + grp * GQ;
    const int base = h * HSIZE;
    const int tid = threadIdx.x;
    const int w = tid >> 5;
    const int lane = tid & 31;
    const unsigned ltm = (1u << lane) - 1;

    // ---- union (warp 0) ----
    if (small) {
        if (tid == 0) S.ucnt = 64;
        if (tid < 64) S.uidx[tid] = tid;
    } else if (w == 0) {
        const int tmin = t0;
        const int tmax = t0 + GQ - 1;
        int cmin = 0, kept = 0;
        for (int b = 0; b < T_DIM && cmin < 64; b += 32) {
            int sidx = g_sorted[b + lane];
            bool vmax = (sidx <= tmax);
            unsigned m = __ballot_sync(0xffffffffu, vmax);
            int before = __popc(m & ltm);
            if (vmax && kept + before < UMAX) S.uidx[kept + before] = sidx;
            kept += __popc(m);
            cmin += __popc(__ballot_sync(0xffffffffu, sidx <= tmin));
        }
        if (kept > UMAX) kept = UMAX;
        if (lane == 0) S.ucnt = kept;
        for (int i = kept + lane; i < UMAX; i += 32) S.uidx[i] = 1 << 30;
    }
    __syncthreads();
    const int ucnt = S.ucnt;

    const uint32_t kbase = smem_to_u32(S.Kc);
    const uint32_t vbase = smem_to_u32(S.Vc);
    const uint32_t qbase = smem_to_u32(S.Qs);
    const uint32_t pbase = smem_to_u32(S.Ps);
    char* kc = reinterpret_cast<char*>(S.Kc);
    char* vc = reinterpret_cast<char*>(S.Vc);
    char* qc = reinterpret_cast<char*>(S.Qs);
    char* pc = reinterpret_cast<char*>(S.Ps);

    // stage K/V (zero-pad to 128 rows), 8 threads/row
    const int c8 = tid & 7;
    for (int r = tid >> 3; r < 128; r += 16) {
        uint4 kk = make_uint4(0, 0, 0, 0), vv = kk;
        if (r < ucnt) {
            int tok = S.uidx[r];
            kk = *((const uint4*)(g_kh + (size_t)tok * C_DIM + base) + c8);
            vv = *((const uint4*)(g_vh + (size_t)tok * C_DIM + base) + c8);
        }
        *reinterpret_cast<uint4*>(kc + SW128(r * 128 + c8 * 16)) = kk;
        *reinterpret_cast<uint4*>(vc + SW128(r * 128 + c8 * 16)) = vv;
    }
    {   // Q: 16 rows x 8 chunks
        int r = tid >> 3;
        uint4 qq = *((const uint4*)(g_qh + (size_t)(t0 + r) * C_DIM + base) + c8);
        *reinterpret_cast<uint4*>(qc + SW128(r * 128 + c8 * 16)) = qq;
    }

    // ---- masks: warp w computes queries w*4 .. w*4+3 ----
    if (!small) {
#pragma unroll
        for (int j = 0; j < 4; j++) {
            const int q = w * 4 + j;
            const int t = t0 + q;
            int cum = 0;
#pragma unroll
            for (int c = 0; c < 4; c++) {
                int val = S.uidx[c * 32 + lane];
                bool f = (val <= t);
                unsigned m = __ballot_sync(0xffffffffu, f);
                int before = __popc(m & ltm) + cum;
                unsigned mm = __ballot_sync(0xffffffffu, f && before < 64);
                if (lane == 0) S.mask[q][c] = mm;
                cum += __popc(m);
            }
        }
    }
    __syncthreads();

    // ---- logits: warp w covers keys [w*32, w*32+32) ----
    float d[4][4];
#pragma unroll
    for (int i = 0; i < 4; i++)
#pragma unroll
        for (int j = 0; j < 4; j++) d[i][j] = 0.f;

    const int a_row = lane & 15;
    const int a_k16 = (lane >> 4) * 16;
    const int b_row = (lane & 7) + ((lane >> 4) & 1) * 8;
    const int b_k16 = ((lane >> 3) & 1) * 16;

#pragma unroll
    for (int ks = 0; ks < 4; ks++) {
        uint32_t aq[4];
        LDSM4(aq, qbase + SW128(a_row * 128 + ks * 32 + a_k16));
        uint32_t bk[2][4];
#pragma unroll
        for (int ni2 = 0; ni2 < 2; ni2++)
            LDSM4(bk[ni2], kbase + SW128((w * 32 + ni2 * 16 + b_row) * 128 + ks * 32 + b_k16));
#pragma unroll
        for (int ni = 0; ni < 4; ni++)
            mma16816(d[ni], aq, &bk[ni >> 1][(ni & 1) * 2]);
    }

    const int g  = lane >> 2;
    const int tg = lane & 3;

    // row max over this warp's 32 keys
    float m0 = -1e30f, m1 = -1e30f;
#pragma unroll
    for (int ni = 0; ni < 4; ni++) {
        m0 = fmaxf(m0, fmaxf(d[ni][0], d[ni][1]));
        m1 = fmaxf(m1, fmaxf(d[ni][2], d[ni][3]));
    }
    m0 = fmaxf(m0, __shfl_xor_sync(0xffffffffu, m0, 1));
    m0 = fmaxf(m0, __shfl_xor_sync(0xffffffffu, m0, 2));
    m1 = fmaxf(m1, __shfl_xor_sync(0xffffffffu, m1, 1));
    m1 = fmaxf(m1, __shfl_xor_sync(0xffffffffu, m1, 2));
    if (tg == 0) { S.pmax[w][g] = m0; S.pmax[w][8 + g] = m1; }
    __syncthreads();
    float gm0 = fmaxf(fmaxf(S.pmax[0][g], S.pmax[1][g]), fmaxf(S.pmax[2][g], S.pmax[3][g]));
    float gm1 = fmaxf(fmaxf(S.pmax[0][8 + g], S.pmax[1][8 + g]), fmaxf(S.pmax[2][8 + g], S.pmax[3][8 + g]));

    // weighted exp
    uint32_t mw0 = 0, mw1 = 0;
    if (!small) { mw0 = S.mask[g][w]; mw1 = S.mask[8 + g][w]; }
    const int tA = t0 + g, tB = t0 + 8 + g;
    float ws0 = 0.f, ws1 = 0.f;
#pragma unroll
    for (int ni = 0; ni < 4; ni++) {
        int colL = ni * 8 + tg * 2;
        int col  = w * 32 + colL;
        float wA0, wA1, wB0, wB1;
        if (small) {
            wA0 = (col < tA) ? 1.f : ((col == tA) ? (float)(64 - tA) : 0.f);
            wA1 = (col + 1 < tA) ? 1.f : ((col + 1 == tA) ? (float)(64 - tA) : 0.f);
            wB0 = (col < tB) ? 1.f : ((col == tB) ? (float)(64 - tB) : 0.f);
            wB1 = (col + 1 < tB) ? 1.f : ((col + 1 == tB) ? (float)(64 - tB) : 0.f);
        } else {
            wA0 = (float)((mw0 >> colL) & 1u);
            wA1 = (float)((mw0 >> (colL + 1)) & 1u);
            wB0 = (float)((mw1 >> colL) & 1u);
            wB1 = (float)((mw1 >> (colL + 1)) & 1u);
        }
        d[ni][0] = expf(d[ni][0] - gm0) * wA0;  ws0 += d[ni][0];
        d[ni][1] = expf(d[ni][1] - gm0) * wA1;  ws0 += d[ni][1];
        d[ni][2] = expf(d[ni][2] - gm1) * wB0;  ws1 += d[ni][2];
        d[ni][3] = expf(d[ni][3] - gm1) * wB1;  ws1 += d[ni][3];
    }
    ws0 += __shfl_xor_sync(0xffffffffu, ws0, 1);
    ws0 += __shfl_xor_sync(0xffffffffu, ws0, 2);
    ws1 += __shfl_xor_sync(0xffffffffu, ws1, 1);
    ws1 += __shfl_xor_sync(0xffffffffu, ws1, 2);
    if (tg == 0) { S.psum[w][g] = ws0; S.psum[w][8 + g] = ws1; }
    __syncthreads();
    float inv0 = 1.f / (S.psum[0][g] + S.psum[1][g] + S.psum[2][g] + S.psum[3][g]);
    float inv1 = 1.f / (S.psum[0][8 + g] + S.psum[1][8 + g] + S.psum[2][8 + g] + S.psum[3][8 + g]);

    // store P (fp16, SW256 rows of 256B) — overlays dead Qs
#pragma unroll
    for (int ni = 0; ni < 4; ni++) {
        int col = w * 32 + ni * 8 + tg * 2;
        *reinterpret_cast<__half2*>(pc + SW256(g * 256 + col * 2)) =
            __floats2half2_rn(d[ni][0] * inv0, d[ni][1] * inv0);
        *reinterpret_cast<__half2*>(pc + SW256((8 + g) * 256 + col * 2)) =
            __floats2half2_rn(d[ni][2] * inv1, d[ni][3] * inv1);
    }
    __syncthreads();

    // ---- PV: warp w covers dims [w*16, w*16+16) ----
    float o[2][4];
#pragma unroll
    for (int i = 0; i < 2; i++)
#pragma unroll
        for (int j = 0; j < 4; j++) o[i][j] = 0.f;

    const int v_row = (lane & 7) + ((lane >> 3) & 1) * 8;
    const int v_d16 = ((lane >> 4) & 1) * 16;

#pragma unroll
    for (int ks = 0; ks < 8; ks++) {
        uint32_t ap[4];
        LDSM4(ap, pbase + SW256(a_row * 256 + ks * 32 + a_k16));
        uint32_t bv[4];
        LDSM4_T(bv, vbase + SW128((ks * 16 + v_row) * 128 + w * 32 + v_d16));
        mma16816(o[0], ap, &bv[0]);
        mma16816(o[1], ap, &bv[2]);
    }

#pragma unroll
    for (int ni = 0; ni < 2; ni++) {
        int col = w * 16 + ni * 8 + tg * 2;
        *reinterpret_cast<__half2*>(g_atq + (size_t)(t0 + g) * C_DIM + base + col) =
            __floats2half2_rn(o[ni][0], o[ni][1]);
        *reinterpret_cast<__half2*>(g_atq + (size_t)(t0 + 8 + g) * C_DIM + base + col) =
            __floats2half2_rn(o[ni][2], o[ni][3]);
    }
}

// ---------------------------------------------------------------------------
extern "C" void kernel_launch(void* const* d_in, const int* in_sizes, int n_in,
                              void* d_out, int out_size)
{
    const float* x   = (const float*)d_in[0];
    const float* Wq  = (const float*)d_in[1];
    const float* bq  = (const float*)d_in[2];
    const float* Wk  = (const float*)d_in[3];
    const float* bk  = (const float*)d_in[4];
    const float* Wv  = (const float*)d_in[5];
    const float* bv  = (const float*)d_in[6];
    const float* Wo  = (const float*)d_in[7];
    const float* bo  = (const float*)d_in[8];
    const float* Wks = (const float*)d_in[9];
    const float* bks = (const float*)d_in[10];
    float* out = (float*)d_out;

    __half *qh, *kh, *vh;
    cudaGetSymbolAddress((void**)&qh, g_qh);
    cudaGetSymbolAddress((void**)&kh, g_kh);
    cudaGetSymbolAddress((void**)&vh, g_vh);

    __half *xq, *wq, *wk, *wv, *wo, *atq;
    cudaGetSymbolAddress((void**)&xq,  g_xq);
    cudaGetSymbolAddress((void**)&wq,  g_wq);
    cudaGetSymbolAddress((void**)&wk,  g_wk);
    cudaGetSymbolAddress((void**)&wv,  g_wv);
    cudaGetSymbolAddress((void**)&wo,  g_wo);
    cudaGetSymbolAddress((void**)&atq, g_atq);

    const int gemm_smem = NSTAGE * STAGE_B;       // 98304
    const int out_smem  = NSTAGE * STAGE_O;       // 73728
    const int attn_smem = (int)sizeof(AttnSmem);  // ~37.3KB
    static bool attr_done = false;
    if (!attr_done) {
        cudaFuncSetAttribute(gemm_qkv, cudaFuncAttributeMaxDynamicSharedMemorySize, gemm_smem);
        cudaFuncSetAttribute(gemm_out, cudaFuncAttributeMaxDynamicSharedMemorySize, out_smem);
        cudaFuncSetAttribute(attn_mma_kernel, cudaFuncAttributeMaxDynamicSharedMemorySize, attn_smem);
        attr_done = true;
    }

    prep_inputs<<<T_DIM + 4 * WBLK, 256>>>(
        (const float4*)x, (uint2*)xq, (const float4*)Wks, bks,
        (const float4*)Wq, (uint2*)wq,
        (const float4*)Wk, (uint2*)wk,
        (const float4*)Wv, (uint2*)wv,
        (const float4*)Wo, (uint2*)wo);

    gemm_qkv<<<dim3(32, 16), 256, gemm_smem>>>(
        xq,
        wq, bq, qh,
        wk, bk, kh,
        wv, bv, vh);

    attn_mma_kernel<<<dim3(NGRP + KSP / GQ, NHEAD), 128, attn_smem>>>();

    gemm_out<<<dim3(8, 32), 256, out_smem>>>(atq, wo, bo, out);
}

// round 16
// speedup vs baseline: 1.1202x; 1.0214x over previous
#include <cuda_runtime.h>
#include <cuda_fp16.h>
#include <cstdint>

#define T_DIM 2048
#define C_DIM 1024
#define NHEAD 16
#define HSIZE 64
#define KSP   64
#define GQ    16
#define UMAX  128
#define NGRP  ((T_DIM - KSP) / GQ)   // 124

// ---------------- scratch (no allocations allowed) ----------------
__device__ __half   g_qh[T_DIM * C_DIM];   // Q in fp16, pre-scaled by 0.125
__device__ __half   g_kh[T_DIM * C_DIM];
__device__ __half   g_vh[T_DIM * C_DIM];
__device__ float    g_scores[T_DIM];
__device__ int      g_sorted[T_DIM];

__device__ __half g_xq[T_DIM * C_DIM];
__device__ __half g_wq[C_DIM * C_DIM];
__device__ __half g_wk[C_DIM * C_DIM];
__device__ __half g_wv[C_DIM * C_DIM];
__device__ __half g_wo[C_DIM * C_DIM];
__device__ __half g_atq[T_DIM * C_DIM];

// ---------------- helpers ----------------
__device__ __forceinline__ uint32_t smem_to_u32(const void* p) {
    uint32_t a;
    asm("{ .reg .u64 t; cvta.to.shared.u64 t, %1; cvt.u32.u64 %0, t; }" : "=r"(a) : "l"(p));
    return a;
}
#define SW128(off) ((off) ^ (((off) >> 3) & 0x70))
#define SW256(off) ((off) ^ (((off) >> 4) & 0x70))

__device__ __forceinline__ void cp16(uint32_t dst, const void* src) {
    asm volatile("cp.async.cg.shared.global [%0], [%1], 16;" :: "r"(dst), "l"(src));
}
#define CP_COMMIT() asm volatile("cp.async.commit_group;" ::: "memory")
#define CP_WAIT(n)  asm volatile("cp.async.wait_group %0;" :: "n"(n) : "memory")

#define LDSM4(r, addr) \
    asm volatile("ldmatrix.sync.aligned.m8n8.x4.shared.b16 {%0,%1,%2,%3}, [%4];" \
        : "=r"((r)[0]), "=r"((r)[1]), "=r"((r)[2]), "=r"((r)[3]) : "r"(addr))
#define LDSM4_T(r, addr) \
    asm volatile("ldmatrix.sync.aligned.m8n8.x4.trans.shared.b16 {%0,%1,%2,%3}, [%4];" \
        : "=r"((r)[0]), "=r"((r)[1]), "=r"((r)[2]), "=r"((r)[3]) : "r"(addr))

__device__ __forceinline__ void mma16816(float* d, const uint32_t* a, const uint32_t* b) {
    asm volatile("mma.sync.aligned.m16n8k16.row.col.f32.f16.f16.f32 "
        "{%0,%1,%2,%3}, {%4,%5,%6,%7}, {%8,%9}, {%0,%1,%2,%3};"
        : "+f"(d[0]), "+f"(d[1]), "+f"(d[2]), "+f"(d[3])
        : "r"(a[0]), "r"(a[1]), "r"(a[2]), "r"(a[3]), "r"(b[0]), "r"(b[1]));
}

// ---------------------------------------------------------------------------
// Fused input prep: blocks [0, 2048): x->fp16 + key scores;
// blocks [2048, 4096): weights, 2 float4 per thread.
// ---------------------------------------------------------------------------
#define NW4 (C_DIM * C_DIM / 4)      // 262144 float4 per weight
#define WBLK2 (NW4 / 512)            // 512 blocks per weight (2 f4/thread)

__global__ __launch_bounds__(256) void prep_inputs(
    const float4* __restrict__ x4, uint2* __restrict__ xq,
    const float4* __restrict__ wks4, const float* __restrict__ bks,
    const float4* __restrict__ w0, uint2* __restrict__ d0,
    const float4* __restrict__ w1, uint2* __restrict__ d1,
    const float4* __restrict__ w2, uint2* __restrict__ d2,
    const float4* __restrict__ w3, uint2* __restrict__ d3)
{
    const int tid = threadIdx.x;
    const int bx = blockIdx.x;

    if (bx < T_DIM) {
        const int i = bx * 256 + tid;
        float4 v = x4[i];
        __half2 p0 = __floats2half2_rn(v.x, v.y);
        __half2 p1 = __floats2half2_rn(v.z, v.w);
        xq[i] = make_uint2(*reinterpret_cast<uint32_t*>(&p0), *reinterpret_cast<uint32_t*>(&p1));

        float4 wk = wks4[tid];
        float s = v.x * wk.x + v.y * wk.y + v.z * wk.z + v.w * wk.w;
#pragma unroll
        for (int o = 16; o; o >>= 1) s += __shfl_down_sync(0xffffffffu, s, o);
        __shared__ float red[8];
        if ((tid & 31) == 0) red[tid >> 5] = s;
        __syncthreads();
        if (tid == 0) {
            float tot = 0.f;
#pragma unroll
            for (int j = 0; j < 8; j++) tot += red[j];
            g_scores[bx] = tot + bks[0];
        }
    } else {
        const int idx = bx - T_DIM;
        const int which = idx / WBLK2;
        const int i0 = (idx % WBLK2) * 512 + tid;
        const float4* src = (which == 0) ? w0 : (which == 1) ? w1 : (which == 2) ? w2 : w3;
        uint2* dst = (which == 0) ? d0 : (which == 1) ? d1 : (which == 2) ? d2 : d3;
        float4 v0 = src[i0];
        float4 v1 = src[i0 + 256];
        __half2 a0 = __floats2half2_rn(v0.x, v0.y);
        __half2 b0 = __floats2half2_rn(v0.z, v0.w);
        __half2 a1 = __floats2half2_rn(v1.x, v1.y);
        __half2 b1 = __floats2half2_rn(v1.z, v1.w);
        dst[i0] = make_uint2(*reinterpret_cast<uint32_t*>(&a0), *reinterpret_cast<uint32_t*>(&b0));
        dst[i0 + 256] = make_uint2(*reinterpret_cast<uint32_t*>(&a1), *reinterpret_cast<uint32_t*>(&b1));
    }
}

// ---------------------------------------------------------------------------
// Rank-sort body (rides inside gemm_qkv's grid)
// ---------------------------------------------------------------------------
__device__ __forceinline__ void rank_body(char* smem, int rb)
{
    float* ss = reinterpret_cast<float*>(smem);
    const int tid = threadIdx.x;
    for (int i = tid; i < T_DIM; i += 256) ss[i] = g_scores[i];
    __syncthreads();

    const int grpl = tid >> 4;
    const int sub  = tid & 15;
    const int tok = rb * 16 + grpl;
    const float si = ss[tok];

    const float4* s4 = reinterpret_cast<const float4*>(ss);
    int cnt = 0;
    const int j0 = sub * 32;
#pragma unroll 8
    for (int j4 = j0; j4 < j0 + 32; j4++) {
        float4 v = s4[j4];
        int j = j4 << 2;
        cnt += (v.x > si) || (v.x == si && (j + 0) < tok);
        cnt += (v.y > si) || (v.y == si && (j + 1) < tok);
        cnt += (v.z > si) || (v.z == si && (j + 2) < tok);
        cnt += (v.w > si) || (v.w == si && (j + 3) < tok);
    }
#pragma unroll
    for (int o = 8; o; o >>= 1) cnt += __shfl_down_sync(0xffffffffu, cnt, o, 16);
    if (sub == 0) g_sorted[cnt] = tok;
}

// ---------------------------------------------------------------------------
// HMMA GEMM core (128x128): D = (Ax*B + bias) * scale. 3-stage, 2 CTAs/SM.
// ---------------------------------------------------------------------------
#define NCHUNK  (C_DIM / 64)
#define TILE_B  16384
#define STAGE_B 32768
#define NSTAGE  3
#define RU      (C_DIM / 8)

template <bool HALF_OUT>
__device__ __forceinline__ void gemm_core(
    const __half* Ax, const __half* B,
    const float* bias, void* outp, int bm, int bn, char* smem, float scale)
{
    const uint32_t sb = smem_to_u32(smem);
    const int tid = threadIdx.x;
    const int wid = tid >> 5;
    const int lane = tid & 31;
    const int warp_m = wid & 3;
    const int warp_n = wid >> 2;

    float acc[2][8][4];
#pragma unroll
    for (int i = 0; i < 2; i++)
#pragma unroll
        for (int j = 0; j < 8; j++)
#pragma unroll
            for (int q = 0; q < 4; q++) acc[i][j][q] = 0.f;

    const uint4* srcs[2] = {
        reinterpret_cast<const uint4*>(Ax) + (size_t)bm * RU,
        reinterpret_cast<const uint4*>(B)  + (size_t)bn * RU };

    const int lrow = tid >> 3;
    const int lch  = tid & 7;

    auto issue = [&](int s, int c) {
        const int kq = c * 8;
        const uint32_t sbase = sb + s * STAGE_B;
#pragma unroll
        for (int t2 = 0; t2 < 2; t2++) {
            const uint4* srow = srcs[t2] + kq;
            const uint32_t dbase = sbase + t2 * TILE_B;
#pragma unroll
            for (int p = 0; p < 4; p++) {
                int row = lrow + p * 32;
                cp16(dbase + SW128(row * 128 + lch * 16),
                     srow + (size_t)row * RU + lch);
            }
        }
        CP_COMMIT();
    };

    issue(0, 0);
    issue(1, 1);
    issue(2, 2);

    const int a_row  = warp_m * 32 + (lane & 15);
    const int a_koff = (lane >> 4) * 16;
    const int b_row  = warp_n * 64 + (lane & 7) + ((lane >> 4) & 1) * 8;
    const int b_koff = ((lane >> 3) & 1) * 16;

    for (int c = 0; c < NCHUNK; c++) {
        const int s = c % NSTAGE;
        if (c < NCHUNK - 2)       { CP_WAIT(2); }
        else if (c == NCHUNK - 2) { CP_WAIT(1); }
        else                      { CP_WAIT(0); }
        __syncthreads();

        const uint32_t aX = sb + s * STAGE_B;
        const uint32_t bB = aX + TILE_B;

#pragma unroll
        for (int ks = 0; ks < 4; ks++) {
            const int akb = ks * 32 + a_koff;
            const int bkb = ks * 32 + b_koff;
            uint32_t ax[2][4], bb[4][4];
#pragma unroll
            for (int mi = 0; mi < 2; mi++) {
                int off = (a_row + mi * 16) * 128 + akb;
                LDSM4(ax[mi], aX + SW128(off));
            }
#pragma unroll
            for (int ni2 = 0; ni2 < 4; ni2++) {
                int off = (b_row + ni2 * 16) * 128 + bkb;
                LDSM4(bb[ni2], bB + SW128(off));
            }
#pragma unroll
            for (int mi = 0; mi < 2; mi++)
#pragma unroll
                for (int ni = 0; ni < 8; ni++)
                    mma16816(acc[mi][ni], ax[mi], &bb[ni >> 1][(ni & 1) * 2]);
        }
        __syncthreads();
        if (c + NSTAGE < NCHUNK) issue(s, c + NSTAGE);
    }

    const int g  = lane >> 2;
    const int tg = lane & 3;
#pragma unroll
    for (int mi = 0; mi < 2; mi++) {
        const int row = bm + warp_m * 32 + mi * 16 + g;
#pragma unroll
        for (int ni = 0; ni < 8; ni++) {
            const int col = bn + warp_n * 64 + ni * 8 + tg * 2;
            float2 bv = *reinterpret_cast<const float2*>(bias + col);
            float o00 = (acc[mi][ni][0] + bv.x) * scale, o01 = (acc[mi][ni][1] + bv.y) * scale;
            float o10 = (acc[mi][ni][2] + bv.x) * scale, o11 = (acc[mi][ni][3] + bv.y) * scale;
            if (HALF_OUT) {
                __half* out = (__half*)outp;
                __half2 h0 = __floats2half2_rn(o00, o01);
                __half2 h1 = __floats2half2_rn(o10, o11);
                *reinterpret_cast<__half2*>(out + (size_t)row * C_DIM + col) = h0;
                *reinterpret_cast<__half2*>(out + (size_t)(row + 8) * C_DIM + col) = h1;
            } else {
                float* out = (float*)outp;
                *reinterpret_cast<float2*>(out + (size_t)row * C_DIM + col) = make_float2(o00, o01);
                *reinterpret_cast<float2*>(out + (size_t)(row + 8) * C_DIM + col) = make_float2(o10, o11);
            }
        }
    }
}

// Fused QKV + rank: grid (32, 16). nb<24: GEMM tiles; nb>=24: rank blocks.
__global__ __launch_bounds__(256, 2) void gemm_qkv(
    const __half* Ax,
    const __half* B0, const float* bias0, __half* out0,
    const __half* B1, const float* bias1, __half* out1,
    const __half* B2, const float* bias2, __half* out2)
{
    extern __shared__ char smem[];
    const int nb = blockIdx.x;
    if (nb >= 24) {
        rank_body(smem, (nb - 24) + blockIdx.y * 8);
        return;
    }
    const int which = nb >> 3;
    const int bn = (nb & 7) << 7;
    const int bm = blockIdx.y << 7;
    if (which == 0) {
        gemm_core<true>(Ax, B0, bias0, out0, bm, bn, smem, 0.125f);  // Q pre-scaled
    } else if (which == 1) {
        gemm_core<true>(Ax, B1, bias1, out1, bm, bn, smem, 1.0f);
    } else {
        gemm_core<true>(Ax, B2, bias2, out2, bm, bn, smem, 1.0f);
    }
}

// ---------------------------------------------------------------------------
// Output GEMM: BM=64, BN=128 tiles, grid (8, 32) = 256 CTAs, 3 CTAs/SM.
// 8 warps as 2m x 4n, warp tile 32x32. Stage = 24KB (A 8KB + B 16KB).
// ---------------------------------------------------------------------------
#define ATILE_O 8192
#define STAGE_O 24576

__global__ __launch_bounds__(256, 3) void gemm_out(
    const __half* __restrict__ Ax, const __half* __restrict__ B,
    const float* __restrict__ bias, float* __restrict__ out)
{
    extern __shared__ char smem[];
    const uint32_t sb = smem_to_u32(smem);
    const int tid = threadIdx.x;
    const int wid = tid >> 5;
    const int lane = tid & 31;
    const int warp_m = wid & 1;
    const int warp_n = wid >> 1;
    const int bm = blockIdx.y << 6;
    const int bn = blockIdx.x << 7;

    float acc[2][4][4];
#pragma unroll
    for (int i = 0; i < 2; i++)
#pragma unroll
        for (int j = 0; j < 4; j++)
#pragma unroll
            for (int q = 0; q < 4; q++) acc[i][j][q] = 0.f;

    const uint4* srcA = reinterpret_cast<const uint4*>(Ax) + (size_t)bm * RU;
    const uint4* srcB = reinterpret_cast<const uint4*>(B)  + (size_t)bn * RU;

    const int lrow = tid >> 3;   // 0..31
    const int lch  = tid & 7;

    auto issue = [&](int s, int c) {
        const int kq = c * 8;
        const uint32_t sbase = sb + s * STAGE_O;
#pragma unroll
        for (int p = 0; p < 2; p++) {       // A: 64 rows
            int row = lrow + p * 32;
            cp16(sbase + SW128(row * 128 + lch * 16),
                 srcA + (size_t)row * RU + kq + lch);
        }
#pragma unroll
        for (int p = 0; p < 4; p++) {       // B: 128 rows
            int row = lrow + p * 32;
            cp16(sbase + ATILE_O + SW128(row * 128 + lch * 16),
                 srcB + (size_t)row * RU + kq + lch);
        }
        CP_COMMIT();
    };

    issue(0, 0);
    issue(1, 1);
    issue(2, 2);

    const int a_row  = warp_m * 32 + (lane & 15);
    const int a_koff = (lane >> 4) * 16;
    const int b_row  = warp_n * 32 + (lane & 7) + ((lane >> 4) & 1) * 8;
    const int b_koff = ((lane >> 3) & 1) * 16;

    for (int c = 0; c < NCHUNK; c++) {
        const int s = c % NSTAGE;
        if (c < NCHUNK - 2)       { CP_WAIT(2); }
        else if (c == NCHUNK - 2) { CP_WAIT(1); }
        else                      { CP_WAIT(0); }
        __syncthreads();

        const uint32_t aX = sb + s * STAGE_O;
        const uint32_t bB = aX + ATILE_O;

#pragma unroll
        for (int ks = 0; ks < 4; ks++) {
            const int akb = ks * 32 + a_koff;
            const int bkb = ks * 32 + b_koff;
            uint32_t ax[2][4], bb[2][4];
#pragma unroll
            for (int mi = 0; mi < 2; mi++) {
                int off = (a_row + mi * 16) * 128 + akb;
                LDSM4(ax[mi], aX + SW128(off));
            }
#pragma unroll
            for (int ni2 = 0; ni2 < 2; ni2++) {
                int off = (b_row + ni2 * 16) * 128 + bkb;
                LDSM4(bb[ni2], bB + SW128(off));
            }
#pragma unroll
            for (int mi = 0; mi < 2; mi++)
#pragma unroll
                for (int ni = 0; ni < 4; ni++)
                    mma16816(acc[mi][ni], ax[mi], &bb[ni >> 1][(ni & 1) * 2]);
        }
        __syncthreads();
        if (c + NSTAGE < NCHUNK) issue(s, c + NSTAGE);
    }

    const int g  = lane >> 2;
    const int tg = lane & 3;
#pragma unroll
    for (int mi = 0; mi < 2; mi++) {
        const int row = bm + warp_m * 32 + mi * 16 + g;
#pragma unroll
        for (int ni = 0; ni < 4; ni++) {
            const int col = bn + warp_n * 32 + ni * 8 + tg * 2;
            float2 bv = *reinterpret_cast<const float2*>(bias + col);
            *reinterpret_cast<float2*>(out + (size_t)row * C_DIM + col) =
                make_float2(acc[mi][ni][0] + bv.x, acc[mi][ni][1] + bv.y);
            *reinterpret_cast<float2*>(out + (size_t)(row + 8) * C_DIM + col) =
                make_float2(acc[mi][ni][2] + bv.x, acc[mi][ni][3] + bv.y);
        }
    }
}

// ---------------------------------------------------------------------------
// MMA grouped attention (128 thr / 4 warps), union+masks in-block, Ps on Qs.
// ---------------------------------------------------------------------------
struct AttnSmem {
    __half   Kc[128 * 64];   // 16 KB, SW128
    __half   Vc[128 * 64];   // 16 KB, SW128
    union {
        __half Qs[16 * 64];  //  2 KB, SW128 (dead after logits)
        __half Ps[16 * 128]; //  4 KB, SW256
    };
    float    pmax[4][16];
    float    psum[4][16];
    int      uidx[UMAX];
    uint32_t mask[GQ][4];
    int      ucnt;
};

__global__ __launch_bounds__(128, 6) void attn_mma_kernel()
{
    extern __shared__ char sm_raw[];
    AttnSmem& S = *reinterpret_cast<AttnSmem*>(sm_raw);

    const int grp = blockIdx.x;
    const int h   = blockIdx.y;
    const bool small = (grp >= NGRP);
    const int t0  = small ? (grp - NGRP) * GQ : KSP + grp * GQ;
    const int base = h * HSIZE;
    const int tid = threadIdx.x;
    const int w = tid >> 5;
    const int lane = tid & 31;
    const unsigned ltm = (1u << lane) - 1;

    // ---- union (warp 0) ----
    if (small) {
        if (tid == 0) S.ucnt = 64;
        if (tid < 64) S.uidx[tid] = tid;
    } else if (w == 0) {
        const int tmin = t0;
        const int tmax = t0 + GQ - 1;
        int cmin = 0, kept = 0;
        for (int b = 0; b < T_DIM && cmin < 64; b += 32) {
            int sidx = g_sorted[b + lane];
            bool vmax = (sidx <= tmax);
            unsigned m = __ballot_sync(0xffffffffu, vmax);
            int before = __popc(m & ltm);
            if (vmax && kept + before < UMAX) S.uidx[kept + before] = sidx;
            kept += __popc(m);
            cmin += __popc(__ballot_sync(0xffffffffu, sidx <= tmin));
        }
        if (kept > UMAX) kept = UMAX;
        if (lane == 0) S.ucnt = kept;
        for (int i = kept + lane; i < UMAX; i += 32) S.uidx[i] = 1 << 30;
    }
    __syncthreads();
    const int ucnt = S.ucnt;

    const uint32_t kbase = smem_to_u32(S.Kc);
    const uint32_t vbase = smem_to_u32(S.Vc);
    const uint32_t qbase = smem_to_u32(S.Qs);
    const uint32_t pbase = smem_to_u32(S.Ps);
    char* kc = reinterpret_cast<char*>(S.Kc);
    char* vc = reinterpret_cast<char*>(S.Vc);
    char* qc = reinterpret_cast<char*>(S.Qs);
    char* pc = reinterpret_cast<char*>(S.Ps);

    // stage K/V (zero-pad to 128 rows), 8 threads/row
    const int c8 = tid & 7;
    for (int r = tid >> 3; r < 128; r += 16) {
        uint4 kk = make_uint4(0, 0, 0, 0), vv = kk;
        if (r < ucnt) {
            int tok = S.uidx[r];
            kk = *((const uint4*)(g_kh + (size_t)tok * C_DIM + base) + c8);
            vv = *((const uint4*)(g_vh + (size_t)tok * C_DIM + base) + c8);
        }
        *reinterpret_cast<uint4*>(kc + SW128(r * 128 + c8 * 16)) = kk;
        *reinterpret_cast<uint4*>(vc + SW128(r * 128 + c8 * 16)) = vv;
    }
    {   // Q: 16 rows x 8 chunks
        int r = tid >> 3;
        uint4 qq = *((const uint4*)(g_qh + (size_t)(t0 + r) * C_DIM + base) + c8);
        *reinterpret_cast<uint4*>(qc + SW128(r * 128 + c8 * 16)) = qq;
    }

    // ---- masks: warp w computes queries w*4 .. w*4+3 ----
    if (!small) {
#pragma unroll
        for (int j = 0; j < 4; j++) {
            const int q = w * 4 + j;
            const int t = t0 + q;
            int cum = 0;
#pragma unroll
            for (int c = 0; c < 4; c++) {
                int val = S.uidx[c * 32 + lane];
                bool f = (val <= t);
                unsigned m = __ballot_sync(0xffffffffu, f);
                int before = __popc(m & ltm) + cum;
                unsigned mm = __ballot_sync(0xffffffffu, f && before < 64);
                if (lane == 0) S.mask[q][c] = mm;
                cum += __popc(m);
            }
        }
    }
    __syncthreads();

    // ---- logits: warp w covers keys [w*32, w*32+32) ----
    float d[4][4];
#pragma unroll
    for (int i = 0; i < 4; i++)
#pragma unroll
        for (int j = 0; j < 4; j++) d[i][j] = 0.f;

    const int a_row = lane & 15;
    const int a_k16 = (lane >> 4) * 16;
    const int b_row = (lane & 7) + ((lane >> 4) & 1) * 8;
    const int b_k16 = ((lane >> 3) & 1) * 16;

#pragma unroll
    for (int ks = 0; ks < 4; ks++) {
        uint32_t aq[4];
        LDSM4(aq, qbase + SW128(a_row * 128 + ks * 32 + a_k16));
        uint32_t bk[2][4];
#pragma unroll
        for (int ni2 = 0; ni2 < 2; ni2++)
            LDSM4(bk[ni2], kbase + SW128((w * 32 + ni2 * 16 + b_row) * 128 + ks * 32 + b_k16));
#pragma unroll
        for (int ni = 0; ni < 4; ni++)
            mma16816(d[ni], aq, &bk[ni >> 1][(ni & 1) * 2]);
    }

    const int g  = lane >> 2;
    const int tg = lane & 3;

    // row max over this warp's 32 keys
    float m0 = -1e30f, m1 = -1e30f;
#pragma unroll
    for (int ni = 0; ni < 4; ni++) {
        m0 = fmaxf(m0, fmaxf(d[ni][0], d[ni][1]));
        m1 = fmaxf(m1, fmaxf(d[ni][2], d[ni][3]));
    }
    m0 = fmaxf(m0, __shfl_xor_sync(0xffffffffu, m0, 1));
    m0 = fmaxf(m0, __shfl_xor_sync(0xffffffffu, m0, 2));
    m1 = fmaxf(m1, __shfl_xor_sync(0xffffffffu, m1, 1));
    m1 = fmaxf(m1, __shfl_xor_sync(0xffffffffu, m1, 2));
    if (tg == 0) { S.pmax[w][g] = m0; S.pmax[w][8 + g] = m1; }
    __syncthreads();
    float gm0 = fmaxf(fmaxf(S.pmax[0][g], S.pmax[1][g]), fmaxf(S.pmax[2][g], S.pmax[3][g]));
    float gm1 = fmaxf(fmaxf(S.pmax[0][8 + g], S.pmax[1][8 + g]), fmaxf(S.pmax[2][8 + g], S.pmax[3][8 + g]));

    // weighted exp
    uint32_t mw0 = 0, mw1 = 0;
    if (!small) { mw0 = S.mask[g][w]; mw1 = S.mask[8 + g][w]; }
    const int tA = t0 + g, tB = t0 + 8 + g;
    float ws0 = 0.f, ws1 = 0.f;
#pragma unroll
    for (int ni = 0; ni < 4; ni++) {
        int colL = ni * 8 + tg * 2;
        int col  = w * 32 + colL;
        float wA0, wA1, wB0, wB1;
        if (small) {
            wA0 = (col < tA) ? 1.f : ((col == tA) ? (float)(64 - tA) : 0.f);
            wA1 = (col + 1 < tA) ? 1.f : ((col + 1 == tA) ? (float)(64 - tA) : 0.f);
            wB0 = (col < tB) ? 1.f : ((col == tB) ? (float)(64 - tB) : 0.f);
            wB1 = (col + 1 < tB) ? 1.f : ((col + 1 == tB) ? (float)(64 - tB) : 0.f);
        } else {
            wA0 = (float)((mw0 >> colL) & 1u);
            wA1 = (float)((mw0 >> (colL + 1)) & 1u);
            wB0 = (float)((mw1 >> colL) & 1u);
            wB1 = (float)((mw1 >> (colL + 1)) & 1u);
        }
        d[ni][0] = expf(d[ni][0] - gm0) * wA0;  ws0 += d[ni][0];
        d[ni][1] = expf(d[ni][1] - gm0) * wA1;  ws0 += d[ni][1];
        d[ni][2] = expf(d[ni][2] - gm1) * wB0;  ws1 += d[ni][2];
        d[ni][3] = expf(d[ni][3] - gm1) * wB1;  ws1 += d[ni][3];
    }
    ws0 += __shfl_xor_sync(0xffffffffu, ws0, 1);
    ws0 += __shfl_xor_sync(0xffffffffu, ws0, 2);
    ws1 += __shfl_xor_sync(0xffffffffu, ws1, 1);
    ws1 += __shfl_xor_sync(0xffffffffu, ws1, 2);
    if (tg == 0) { S.psum[w][g] = ws0; S.psum[w][8 + g] = ws1; }
    __syncthreads();
    float inv0 = 1.f / (S.psum[0][g] + S.psum[1][g] + S.psum[2][g] + S.psum[3][g]);
    float inv1 = 1.f / (S.psum[0][8 + g] + S.psum[1][8 + g] + S.psum[2][8 + g] + S.psum[3][8 + g]);

    // store P (fp16, SW256 rows of 256B) — overlays dead Qs
#pragma unroll
    for (int ni = 0; ni < 4; ni++) {
        int col = w * 32 + ni * 8 + tg * 2;
        *reinterpret_cast<__half2*>(pc + SW256(g * 256 + col * 2)) =
            __floats2half2_rn(d[ni][0] * inv0, d[ni][1] * inv0);
        *reinterpret_cast<__half2*>(pc + SW256((8 + g) * 256 + col * 2)) =
            __floats2half2_rn(d[ni][2] * inv1, d[ni][3] * inv1);
    }
    __syncthreads();

    // ---- PV: warp w covers dims [w*16, w*16+16) ----
    float o[2][4];
#pragma unroll
    for (int i = 0; i < 2; i++)
#pragma unroll
        for (int j = 0; j < 4; j++) o[i][j] = 0.f;

    const int v_row = (lane & 7) + ((lane >> 3) & 1) * 8;
    const int v_d16 = ((lane >> 4) & 1) * 16;

#pragma unroll
    for (int ks = 0; ks < 8; ks++) {
        uint32_t ap[4];
        LDSM4(ap, pbase + SW256(a_row * 256 + ks * 32 + a_k16));
        uint32_t bv[4];
        LDSM4_T(bv, vbase + SW128((ks * 16 + v_row) * 128 + w * 32 + v_d16));
        mma16816(o[0], ap, &bv[0]);
        mma16816(o[1], ap, &bv[2]);
    }

#pragma unroll
    for (int ni = 0; ni < 2; ni++) {
        int col = w * 16 + ni * 8 + tg * 2;
        *reinterpret_cast<__half2*>(g_atq + (size_t)(t0 + g) * C_DIM + base + col) =
            __floats2half2_rn(o[ni][0], o[ni][1]);
        *reinterpret_cast<__half2*>(g_atq + (size_t)(t0 + 8 + g) * C_DIM + base + col) =
            __floats2half2_rn(o[ni][2], o[ni][3]);
    }
}

// ---------------------------------------------------------------------------
extern "C" void kernel_launch(void* const* d_in, const int* in_sizes, int n_in,
                              void* d_out, int out_size)
{
    const float* x   = (const float*)d_in[0];
    const float* Wq  = (const float*)d_in[1];
    const float* bq  = (const float*)d_in[2];
    const float* Wk  = (const float*)d_in[3];
    const float* bk  = (const float*)d_in[4];
    const float* Wv  = (const float*)d_in[5];
    const float* bv  = (const float*)d_in[6];
    const float* Wo  = (const float*)d_in[7];
    const float* bo  = (const float*)d_in[8];
    const float* Wks = (const float*)d_in[9];
    const float* bks = (const float*)d_in[10];
    float* out = (float*)d_out;

    __half *qh, *kh, *vh;
    cudaGetSymbolAddress((void**)&qh, g_qh);
    cudaGetSymbolAddress((void**)&kh, g_kh);
    cudaGetSymbolAddress((void**)&vh, g_vh);

    __half *xq, *wq, *wk, *wv, *wo, *atq;
    cudaGetSymbolAddress((void**)&xq,  g_xq);
    cudaGetSymbolAddress((void**)&wq,  g_wq);
    cudaGetSymbolAddress((void**)&wk,  g_wk);
    cudaGetSymbolAddress((void**)&wv,  g_wv);
    cudaGetSymbolAddress((void**)&wo,  g_wo);
    cudaGetSymbolAddress((void**)&atq, g_atq);

    const int gemm_smem = NSTAGE * STAGE_B;       // 98304
    const int out_smem  = NSTAGE * STAGE_O;       // 73728
    const int attn_smem = (int)sizeof(AttnSmem);  // ~37.3KB
    static bool attr_done = false;
    if (!attr_done) {
        cudaFuncSetAttribute(gemm_qkv, cudaFuncAttributeMaxDynamicSharedMemorySize, gemm_smem);
        cudaFuncSetAttribute(gemm_out, cudaFuncAttributeMaxDynamicSharedMemorySize, out_smem);
        cudaFuncSetAttribute(attn_mma_kernel, cudaFuncAttributeMaxDynamicSharedMemorySize, attn_smem);
        attr_done = true;
    }

    prep_inputs<<<T_DIM + 4 * WBLK2, 256>>>(
        (const float4*)x, (uint2*)xq, (const float4*)Wks, bks,
        (const float4*)Wq, (uint2*)wq,
        (const float4*)Wk, (uint2*)wk,
        (const float4*)Wv, (uint2*)wv,
        (const float4*)Wo, (uint2*)wo);

    gemm_qkv<<<dim3(32, 16), 256, gemm_smem>>>(
        xq,
        wq, bq, qh,
        wk, bk, kh,
        wv, bv, vh);

    attn_mma_kernel<<<dim3(NGRP + KSP / GQ, NHEAD), 128, attn_smem>>>();

    gemm_out<<<dim3(8, 32), 256, out_smem>>>(atq, wo, bo, out);
}